// round 15
// baseline (speedup 1.0000x reference)
#include <cuda_runtime.h>
#include <cuda_fp16.h>
#include <cstdint>
#include <cstddef>

#define NN 100000
#define RR 4
#define EE 300000
#define HH 64
#define SS 4096
#define PP 2

// ------------------------- scratch (static device globals; no allocs) -------------------------
__device__ float g_deg[RR * NN];                 // raw degree counts (inverse taken inline)
__device__ __half g_xh[(size_t)NN * 64];         // x converted to fp16
__device__ __half g_Ah[(size_t)RR * NN * 64];    // per-relation aggregation, fp16
__device__ float g_Bcat[(size_t)NN * 128];       // combined [B0|B1], COMPACT rows (fp32)
__device__ __half g_h1h[(size_t)NN * HH];        // layer-1 output, COMPACT rows, fp16
__device__ unsigned char g_isseed[NN];
__device__ unsigned char g_need[NN];             // node is src of a seed-destined edge
__device__ int  g_nodes[NN];                     // compacted list of need-nodes
__device__ int  g_map[NN];                       // node -> compact index
__device__ int2 g_se[(size_t)RR * EE];           // compacted seed-destined edges per relation
__device__ int  g_cnt[8];                        // [0..3]=per-rel seed-edge count, [4]=need count
__device__ float g_sA[SS * 128];                 // combined layer-2 features at seeds (fp32)
__device__ float g_h2[SS * HH];
__device__ float g_hs[SS * HH];
__device__ float g_D1[PP * SS * 256];
__device__ float g_D2[PP * SS * 32];
__device__ __half g_F1h[(size_t)PP * SS * 256];  // f1 output, fp16
__device__ __half g_F2h[(size_t)PP * SS * 2048]; // f2 output, fp16

// ------------------------- helpers -------------------------
__device__ __forceinline__ void red_add4h(__half* p, uint32_t a, uint32_t b,
                                          uint32_t c, uint32_t d) {
    asm volatile("red.global.add.noftz.v4.f16x2 [%0], {%1,%2,%3,%4};" ::
                 "l"(p), "r"(a), "r"(b), "r"(c), "r"(d) : "memory");
}

__device__ __forceinline__ uint32_t f2tf(float x) {
    uint32_t u;
    asm("cvt.rna.tf32.f32 %0, %1;" : "=r"(u) : "f"(x));
    return u;
}

__device__ __forceinline__ uint32_t packh2(float a, float b) {
    __half2 h = __floats2half2_rn(a, b);          // low half = a
    return *reinterpret_cast<uint32_t*>(&h);
}

__device__ __forceinline__ void mma_tf32(float* c, const uint32_t* a, const uint32_t* b) {
    asm volatile(
        "mma.sync.aligned.m16n8k8.row.col.f32.tf32.tf32.f32 "
        "{%0,%1,%2,%3},{%4,%5,%6,%7},{%8,%9},{%0,%1,%2,%3};"
        : "+f"(c[0]), "+f"(c[1]), "+f"(c[2]), "+f"(c[3])
        : "r"(a[0]), "r"(a[1]), "r"(a[2]), "r"(a[3]), "r"(b[0]), "r"(b[1]));
}

__device__ __forceinline__ void mma_f16(float* c, const uint32_t* a, const uint32_t* b) {
    asm volatile(
        "mma.sync.aligned.m16n8k16.row.col.f32.f16.f16.f32 "
        "{%0,%1,%2,%3},{%4,%5,%6,%7},{%8,%9},{%0,%1,%2,%3};"
        : "+f"(c[0]), "+f"(c[1]), "+f"(c[2]), "+f"(c[3])
        : "r"(a[0]), "r"(a[1]), "r"(a[2]), "r"(a[3]), "r"(b[0]), "r"(b[1]));
}

// ------------------------- small kernels -------------------------
__global__ void k_seedflag(const int* __restrict__ seeds) {
    int i = blockIdx.x * blockDim.x + threadIdx.x;
    if (i < SS) g_isseed[seeds[i]] = 1;
}

// convert x to fp16 (8 values per thread)
__global__ void k_x2h(const float* __restrict__ x) {
    int i = blockIdx.x * blockDim.x + threadIdx.x;
    if (i >= NN * 8) return;
    float4 a = *reinterpret_cast<const float4*>(&x[(size_t)i * 8]);
    float4 b = *reinterpret_cast<const float4*>(&x[(size_t)i * 8 + 4]);
    uint4 u = make_uint4(packh2(a.x, a.y), packh2(a.z, a.w),
                         packh2(b.x, b.y), packh2(b.z, b.w));
    *reinterpret_cast<uint4*>(&g_xh[(size_t)i * 8]) = u;
}

// single edge pass: degree + warp-aggregated compaction of seed-destined edges + need marks
__global__ void k_edgepass(const int* __restrict__ edges) {
    int e = blockIdx.x * blockDim.x + threadIdx.x;
    if (e >= RR * EE) return;
    int lane = threadIdx.x & 31;
    int r = e / EE;
    int2 ed = reinterpret_cast<const int2*>(edges)[e];
    atomicAdd(&g_deg[r * NN + ed.y], 1.0f);
    bool hit = g_isseed[ed.y] != 0;
    unsigned mask = __ballot_sync(0xffffffffu, hit);
    if (hit) {
        g_need[ed.x] = 1;
        int leader = __ffs(mask) - 1;
        int pos = 0;
        if (lane == leader) pos = atomicAdd(&g_cnt[r], __popc(mask));
        pos = __shfl_sync(mask, pos, leader);
        pos += __popc(mask & ((1u << lane) - 1u));
        g_se[(size_t)r * EE + pos] = ed;
    }
}

// warp-aggregated need-node compaction
__global__ void k_nodecount() {
    int n = blockIdx.x * blockDim.x + threadIdx.x;
    if (n >= NN) return;
    int lane = threadIdx.x & 31;
    bool need = g_need[n] != 0;
    unsigned mask = __ballot_sync(0xffffffffu, need);
    if (need) {
        int leader = __ffs(mask) - 1;
        int pos = 0;
        if (lane == leader) pos = atomicAdd(&g_cnt[4], __popc(mask));
        pos = __shfl_sync(mask, pos, leader);
        pos += __popc(mask & ((1u << lane) - 1u));
        g_nodes[pos] = n;
        g_map[n] = pos;
    }
}

// zero A rows of listed nodes (8 threads per node; 16B per (thread, r))
__global__ void k_zeroA() {
    int total = g_cnt[4] * 8;
    int stride = gridDim.x * blockDim.x;
    for (int t = blockIdx.x * blockDim.x + threadIdx.x; t < total; t += stride) {
        int e = t >> 3, i8 = t & 7;
        int n = g_nodes[e];
#pragma unroll
        for (int r = 0; r < RR; r++)
            *reinterpret_cast<uint4*>(&g_Ah[((size_t)r * NN + n) * 64 + i8 * 8]) =
                make_uint4(0u, 0u, 0u, 0u);
    }
}

// layer-1 scatter: A[r][dst] += xh[src] for needed dsts. 8 lanes/edge, 2 edges/thread.
__global__ void k_scatterA(const int* __restrict__ edges) {
    int gid = blockIdx.x * blockDim.x + threadIdx.x;
    int l = gid & 7;
    int e0 = (gid >> 3) * 2;
    if (e0 >= RR * EE) return;
    const int2* E = reinterpret_cast<const int2*>(edges);
    int2 ed0 = E[e0];
    int2 ed1 = E[e0 + 1];
    bool n0 = g_need[ed0.y] != 0;
    bool n1 = g_need[ed1.y] != 0;
    uint4 x0 = make_uint4(0u, 0u, 0u, 0u), x1 = x0;
    if (n0) x0 = *reinterpret_cast<const uint4*>(&g_xh[(size_t)ed0.x * 64 + l * 8]);
    if (n1) x1 = *reinterpret_cast<const uint4*>(&g_xh[(size_t)ed1.x * 64 + l * 8]);
    int r0 = e0 / EE, r1 = (e0 + 1) / EE;
    if (n0) red_add4h(&g_Ah[((size_t)r0 * NN + ed0.y) * 64 + l * 8], x0.x, x0.y, x0.z, x0.w);
    if (n1) red_add4h(&g_Ah[((size_t)r1 * NN + ed1.y) * 64 + l * 8], x1.x, x1.y, x1.z, x1.w);
}

// layer-2 scatter over compacted seed-edge lists; h1h is COMPACT fp16 (row = g_map[node])
__global__ void k_scatterList() {
    int gid = blockIdx.x * blockDim.x + threadIdx.x;
    int l = gid & 7;
    int chunk = gid >> 3;
    int nchunks = (gridDim.x * blockDim.x) >> 3;
#pragma unroll
    for (int r = 0; r < RR; r++) {
        int c = g_cnt[r];
        for (int e = chunk; e < c; e += nchunks) {
            int2 ed = g_se[(size_t)r * EE + e];
            int hc = g_map[ed.x];
            uint4 xv = *reinterpret_cast<const uint4*>(&g_h1h[(size_t)hc * 64 + l * 8]);
            red_add4h(&g_Ah[((size_t)r * NN + ed.y) * 64 + l * 8], xv.x, xv.y, xv.z, xv.w);
        }
    }
}

// BcatC[e, b*64+i] = sum_r C[r,b]/max(deg,1) * Ah[r][n][i]  (8 threads per node)
__global__ void k_combine1(const float* __restrict__ Cmat) {
    int total = g_cnt[4] * 8;
    int stride = gridDim.x * blockDim.x;
    for (int t = blockIdx.x * blockDim.x + threadIdx.x; t < total; t += stride) {
        int e = t >> 3, i8 = t & 7;
        int n = g_nodes[e];
        float o0[8], o1[8];
#pragma unroll
        for (int j = 0; j < 8; j++) { o0[j] = 0.f; o1[j] = 0.f; }
#pragma unroll
        for (int r = 0; r < RR; r++) {
            float inv = 1.0f / fmaxf(__ldg(&g_deg[r * NN + n]), 1.0f);
            float c0 = __ldg(&Cmat[r * 2 + 0]) * inv;
            float c1 = __ldg(&Cmat[r * 2 + 1]) * inv;
            uint4 u = *reinterpret_cast<const uint4*>(&g_Ah[((size_t)r * NN + n) * 64 + i8 * 8]);
            const uint32_t uu[4] = {u.x, u.y, u.z, u.w};
#pragma unroll
            for (int q = 0; q < 4; q++) {
                float2 f = __half22float2(*reinterpret_cast<const __half2*>(&uu[q]));
                o0[2 * q + 0] += c0 * f.x; o0[2 * q + 1] += c0 * f.y;
                o1[2 * q + 0] += c1 * f.x; o1[2 * q + 1] += c1 * f.y;
            }
        }
        *reinterpret_cast<float4*>(&g_Bcat[(size_t)e * 128 + i8 * 8])      = *reinterpret_cast<float4*>(&o0[0]);
        *reinterpret_cast<float4*>(&g_Bcat[(size_t)e * 128 + i8 * 8 + 4])  = *reinterpret_cast<float4*>(&o0[4]);
        *reinterpret_cast<float4*>(&g_Bcat[(size_t)e * 128 + 64 + i8 * 8]) = *reinterpret_cast<float4*>(&o1[0]);
        *reinterpret_cast<float4*>(&g_Bcat[(size_t)e * 128 + 64 + i8 * 8 + 4]) = *reinterpret_cast<float4*>(&o1[4]);
    }
}

// zero A rows for seed nodes (8 threads per (seed, r))
__global__ void k_zeroAseed(const int* __restrict__ seeds) {
    int idx = blockIdx.x * blockDim.x + threadIdx.x;
    if (idx >= SS * RR * 8) return;
    int s = idx >> 5;
    int r = (idx >> 3) & 3;
    int i8 = idx & 7;
    int node = seeds[s];
    *reinterpret_cast<uint4*>(&g_Ah[((size_t)r * NN + node) * 64 + i8 * 8]) =
        make_uint4(0u, 0u, 0u, 0u);
}

// sA[s, b*64+i] = sum_r C2[r,b]/max(deg,1) * Ah[r][node][i]  (8 threads per seed)
__global__ void k_combine2(const float* __restrict__ Cmat, const int* __restrict__ seeds) {
    int idx = blockIdx.x * blockDim.x + threadIdx.x;
    if (idx >= SS * 8) return;
    int s = idx >> 3, i8 = idx & 7;
    int n = seeds[s];
    float o0[8], o1[8];
#pragma unroll
    for (int j = 0; j < 8; j++) { o0[j] = 0.f; o1[j] = 0.f; }
#pragma unroll
    for (int r = 0; r < RR; r++) {
        float inv = 1.0f / fmaxf(__ldg(&g_deg[r * NN + n]), 1.0f);
        float c0 = __ldg(&Cmat[r * 2 + 0]) * inv;
        float c1 = __ldg(&Cmat[r * 2 + 1]) * inv;
        uint4 u = *reinterpret_cast<const uint4*>(&g_Ah[((size_t)r * NN + n) * 64 + i8 * 8]);
        const uint32_t uu[4] = {u.x, u.y, u.z, u.w};
#pragma unroll
        for (int q = 0; q < 4; q++) {
            float2 f = __half22float2(*reinterpret_cast<const __half2*>(&uu[q]));
            o0[2 * q + 0] += c0 * f.x; o0[2 * q + 1] += c0 * f.y;
            o1[2 * q + 0] += c1 * f.x; o1[2 * q + 1] += c1 * f.y;
        }
    }
    *reinterpret_cast<float4*>(&g_sA[(size_t)s * 128 + i8 * 8])          = *reinterpret_cast<float4*>(&o0[0]);
    *reinterpret_cast<float4*>(&g_sA[(size_t)s * 128 + i8 * 8 + 4])      = *reinterpret_cast<float4*>(&o0[4]);
    *reinterpret_cast<float4*>(&g_sA[(size_t)s * 128 + 64 + i8 * 8])     = *reinterpret_cast<float4*>(&o1[0]);
    *reinterpret_cast<float4*>(&g_sA[(size_t)s * 128 + 64 + i8 * 8 + 4]) = *reinterpret_cast<float4*>(&o1[4]);
}

__global__ void k_d3(const float* __restrict__ Wd3, const float* __restrict__ bd3,
                     float* __restrict__ out) {
    int i = blockIdx.x * blockDim.x + threadIdx.x;
    if (i >= PP * SS) return;
    int p = i / SS;
    const float* v = &g_D2[(size_t)i * 32];
    const float* w = &Wd3[p * 32];
    float sum = bd3[p];
#pragma unroll
    for (int k = 0; k < 32; k++) sum += v[k] * w[k];
    out[i] = fmaxf(sum, 0.0f);
}

// ------------------------- fp16 tensor-core GEMM (big f-branch layers) -------------------------
// A is fp16 [M,K] (strA in half elements). W fp32 [K,N]. C: fp32, or fp16 when halfOut!=0
// (then C is reinterpreted as packed half2 words, pitch N/2 words, strC in float/uint32 units).
template <int BN, int WM, int WN, int MINB>
__global__ __launch_bounds__(32 * (128 / WM) * (BN / WN), MINB)
void hmma_gemm(const __half* __restrict__ A, size_t strA,
               const float* __restrict__ W, size_t strW,
               const float* __restrict__ bias, size_t strBias,
               float* __restrict__ C, size_t strC,
               int M, int N, int K, int act, int halfOut) {
    constexpr int BM = 128, BK = 32;
    constexpr int MT = WM / 16, NT = WN / 8;
    constexpr int WARPS_M = BM / WM;
    constexpr int NTH = 32 * WARPS_M * (BN / WN);
    constexpr int AGRP = 132;
    constexpr int BGRP = 68;
    constexpr int AWORDS = (BM / 16) * (BK / 16) * AGRP;
    constexpr int BWORDS = (BK / 16) * (BN / 8) * BGRP;
    constexpr int A4H = BM * BK / 8 / NTH;          // uint4 (8 halves) A loads per thread
    constexpr int BU = (BK / 2) * (BN / 4) / NTH;

    __shared__ uint32_t As[2][AWORDS];
    __shared__ uint32_t Bs[2][BWORDS];

    int tid = threadIdx.x, lane = tid & 31, wid = tid >> 5;
    int g = lane >> 2, t4 = lane & 3;
    int wm = (wid % WARPS_M) * WM;
    int wn = (wid / WARPS_M) * WN;

    int p = blockIdx.z;
    A    += (size_t)p * strA;
    W    += (size_t)p * strW;
    C    += (size_t)p * strC;
    const float* bp = bias + (size_t)p * strBias;

    int row0 = blockIdx.y * BM, col0 = blockIdx.x * BN;

    float acc[MT][NT][4];
#pragma unroll
    for (int mt = 0; mt < MT; mt++)
#pragma unroll
        for (int nt = 0; nt < NT; nt++)
#pragma unroll
            for (int i = 0; i < 4; i++) acc[mt][nt][i] = 0.f;

    uint4 va[A4H];
    float4 vb0[BU], vb1[BU];

    auto ldg_tile = [&](int kt) {
#pragma unroll
        for (int i = 0; i < A4H; i++) {
            int idx = tid + i * NTH;
            int r = idx >> 2;                 // 4 uint4 per 32-k row
            int c8 = (idx & 3) * 8;
            int gr = row0 + r;
            va[i] = (gr < M) ? *reinterpret_cast<const uint4*>(&A[(size_t)gr * K + kt + c8])
                             : make_uint4(0u, 0u, 0u, 0u);
        }
#pragma unroll
        for (int u = 0; u < BU; u++) {
            int uidx = tid + u * NTH;
            int kp = uidx / (BN / 4);
            int c4 = (uidx % (BN / 4)) * 4;
            int gc = col0 + c4;
            if (gc < N) {
                vb0[u] = *reinterpret_cast<const float4*>(&W[(size_t)(kt + 2 * kp) * N + gc]);
                vb1[u] = *reinterpret_cast<const float4*>(&W[(size_t)(kt + 2 * kp + 1) * N + gc]);
            } else {
                vb0[u] = make_float4(0.f, 0.f, 0.f, 0.f);
                vb1[u] = vb0[u];
            }
        }
    };
    auto sts_tile = [&](int buf) {
#pragma unroll
        for (int i = 0; i < A4H; i++) {
            int idx = tid + i * NTH;
            int r = idx >> 2;
            int c8 = (idx & 3) * 8;
            const uint32_t w[4] = {va[i].x, va[i].y, va[i].z, va[i].w};
#pragma unroll
            for (int j = 0; j < 4; j++) {
                int kp = (c8 >> 1) + j;                    // global pair index in tile
                int grp = (r >> 4) * (BK / 16) + (kp >> 3);
                int k2p = kp & 7;
                int reg = ((r >> 3) & 1) + (((k2p >> 2) & 1) << 1);
                As[buf][grp * AGRP + ((r & 7) * 4 + (k2p & 3)) * 4 + reg] = w[j];
            }
        }
#pragma unroll
        for (int u = 0; u < BU; u++) {
            int uidx = tid + u * NTH;
            int kp = uidx / (BN / 4);
            int c4 = (uidx % (BN / 4)) * 4;
            int k2p = kp & 7;
            int reg = (k2p >> 2) & 1;
            float w0[4] = {vb0[u].x, vb0[u].y, vb0[u].z, vb0[u].w};
            float w1[4] = {vb1[u].x, vb1[u].y, vb1[u].z, vb1[u].w};
#pragma unroll
            for (int j = 0; j < 4; j++) {
                int c = c4 + j;
                int grp = (kp >> 3) * (BN / 8) + (c >> 3);
                int off = grp * BGRP + ((c & 7) * 4 + (k2p & 3)) * 2 + reg;
                Bs[buf][off] = packh2(w0[j], w1[j]);
            }
        }
    };

    int ntiles = K / BK;
    ldg_tile(0);
    sts_tile(0);
    __syncthreads();
    int cur = 0;

    for (int kt = 0; kt < ntiles; kt++) {
        if (kt + 1 < ntiles) ldg_tile((kt + 1) * BK);
#pragma unroll
        for (int ksb = 0; ksb < BK / 16; ksb++) {
            uint4 af[MT];
            uint2 bf[NT];
#pragma unroll
            for (int mt = 0; mt < MT; mt++)
                af[mt] = *reinterpret_cast<const uint4*>(
                    &As[cur][(((wm >> 4) + mt) * (BK / 16) + ksb) * AGRP + lane * 4]);
#pragma unroll
            for (int nt = 0; nt < NT; nt++)
                bf[nt] = *reinterpret_cast<const uint2*>(
                    &Bs[cur][(ksb * (BN / 8) + (wn >> 3) + nt) * BGRP + lane * 2]);
#pragma unroll
            for (int mt = 0; mt < MT; mt++)
#pragma unroll
                for (int nt = 0; nt < NT; nt++)
                    mma_f16(acc[mt][nt], reinterpret_cast<const uint32_t*>(&af[mt]),
                            reinterpret_cast<const uint32_t*>(&bf[nt]));
        }
        if (kt + 1 < ntiles) {
            sts_tile(cur ^ 1);
            __syncthreads();
            cur ^= 1;
        }
    }

#pragma unroll
    for (int mt = 0; mt < MT; mt++) {
#pragma unroll
        for (int nt = 0; nt < NT; nt++) {
            int gc = col0 + wn + nt * 8 + t4 * 2;
            if (gc >= N) continue;
            float bias0 = bp[gc];
            float bias1 = bp[gc + 1];
#pragma unroll
            for (int h = 0; h < 2; h++) {
                int gr = row0 + wm + mt * 16 + g + h * 8;
                if (gr >= M) continue;
                float v0 = acc[mt][nt][2 * h + 0] + bias0;
                float v1 = acc[mt][nt][2 * h + 1] + bias1;
                if (act == 1) { v0 = fmaxf(v0, 0.f); v1 = fmaxf(v1, 0.f); }
                else          { v0 = tanhf(v0); v1 = tanhf(v1); }
                if (halfOut)
                    reinterpret_cast<uint32_t*>(C)[(size_t)gr * (N >> 1) + (gc >> 1)] =
                        packh2(v0, v1);
                else
                    *reinterpret_cast<float2*>(&C[(size_t)gr * N + gc]) = make_float2(v0, v1);
            }
        }
    }
}

// ------------------------- tf32 mma.sync GEMM (small/medium layers) -------------------------
// halfOut != 0: C is a __half buffer (pitch N halfs); packed half2 stores.
template <int BN, int WM, int WN, int MINB>
__global__ __launch_bounds__(32 * (128 / WM) * (BN / WN), MINB)
void mma_gemm(const float* __restrict__ A, size_t strA,
              const float* __restrict__ W, size_t strW,
              const float* __restrict__ bias, size_t strBias, int hasBias,
              float* __restrict__ C, size_t strC,
              int M, int N, int K, int act,
              const float* __restrict__ gnoise, const int* __restrict__ gseeds,
              const int* __restrict__ Mdev, int halfOut) {
    constexpr int BM = 128, BK = 16;
    constexpr int MT = WM / 16, NT = WN / 8;
    constexpr int WARPS_M = BM / WM;
    constexpr int NTH = 32 * WARPS_M * (BN / WN);
    constexpr int AGRP = 132;
    constexpr int BGRP = 68;
    constexpr int AWORDS = (BM / 16) * (BK / 8) * AGRP;
    constexpr int BWORDS = (BK / 8) * (BN / 8) * BGRP;
    constexpr int A4 = BM * BK / 4 / NTH;
    constexpr int B4 = BK * BN / 4 / NTH;

    __shared__ uint32_t As[2][AWORDS];
    __shared__ uint32_t Bs[2][BWORDS];

    int tid = threadIdx.x, lane = tid & 31, wid = tid >> 5;
    int g = lane >> 2, t4 = lane & 3;
    int wm = (wid % WARPS_M) * WM;
    int wn = (wid / WARPS_M) * WN;

    int p = blockIdx.z;
    A += (size_t)p * strA;
    W += (size_t)p * strW;
    C += (size_t)p * strC;
    const float* bp = hasBias ? (bias + (size_t)p * strBias) : nullptr;

    int row0 = blockIdx.y * BM, col0 = blockIdx.x * BN;

    int Ml = M;
    if (Mdev) {
        Ml = *Mdev;
        if (row0 >= Ml) return;
    }

    float acc[MT][NT][4];
#pragma unroll
    for (int mt = 0; mt < MT; mt++)
#pragma unroll
        for (int nt = 0; nt < NT; nt++)
#pragma unroll
            for (int i = 0; i < 4; i++) acc[mt][nt][i] = 0.f;

    float4 va[A4], vb[B4];

    auto ldg_tile = [&](int kt) {
#pragma unroll
        for (int i = 0; i < A4; i++) {
            int idx = tid + i * NTH;
            int r = idx >> 2;
            int c4 = (idx & 3) * 4;
            int gr = row0 + r;
            va[i] = (gr < Ml) ? *reinterpret_cast<const float4*>(&A[(size_t)gr * K + kt + c4])
                              : make_float4(0.f, 0.f, 0.f, 0.f);
        }
#pragma unroll
        for (int i = 0; i < B4; i++) {
            int idx = tid + i * NTH;
            int r = idx / (BN / 4);
            int c4 = (idx % (BN / 4)) * 4;
            int gc = col0 + c4;
            vb[i] = (gc < N) ? *reinterpret_cast<const float4*>(&W[(size_t)(kt + r) * N + gc])
                             : make_float4(0.f, 0.f, 0.f, 0.f);
        }
    };
    auto sts_tile = [&](int buf) {
#pragma unroll
        for (int i = 0; i < A4; i++) {
            int idx = tid + i * NTH;
            int r = idx >> 2;
            int c4 = (idx & 3) * 4;
            int grp = ((r >> 4) * (BK / 8) + (c4 >> 3)) * AGRP;
            int reg = ((r >> 3) & 1) + (((c4 >> 2) & 1) << 1);
            int gg = r & 7;
            float f[4] = {va[i].x, va[i].y, va[i].z, va[i].w};
#pragma unroll
            for (int j = 0; j < 4; j++)
                As[buf][grp + (gg * 4 + j) * 4 + reg] = f2tf(f[j]);
        }
#pragma unroll
        for (int i = 0; i < B4; i++) {
            int idx = tid + i * NTH;
            int k = idx / (BN / 4);
            int c4 = (idx % (BN / 4)) * 4;
            int grp = ((k >> 3) * (BN / 8) + (c4 >> 3)) * BGRP;
            int reg = (k >> 2) & 1;
            int tt = k & 3;
            float f[4] = {vb[i].x, vb[i].y, vb[i].z, vb[i].w};
#pragma unroll
            for (int j = 0; j < 4; j++)
                Bs[buf][grp + (((c4 & 7) + j) * 4 + tt) * 2 + reg] = f2tf(f[j]);
        }
    };

    int ntiles = K / BK;
    ldg_tile(0);
    sts_tile(0);
    __syncthreads();
    int cur = 0;

    for (int kt = 0; kt < ntiles; kt++) {
        if (kt + 1 < ntiles) ldg_tile((kt + 1) * BK);
#pragma unroll
        for (int ksb = 0; ksb < BK / 8; ksb++) {
            uint4 af[MT];
            uint2 bf[NT];
#pragma unroll
            for (int mt = 0; mt < MT; mt++)
                af[mt] = *reinterpret_cast<const uint4*>(
                    &As[cur][(((wm >> 4) + mt) * (BK / 8) + ksb) * AGRP + lane * 4]);
#pragma unroll
            for (int nt = 0; nt < NT; nt++)
                bf[nt] = *reinterpret_cast<const uint2*>(
                    &Bs[cur][(ksb * (BN / 8) + (wn >> 3) + nt) * BGRP + lane * 2]);
#pragma unroll
            for (int mt = 0; mt < MT; mt++)
#pragma unroll
                for (int nt = 0; nt < NT; nt++)
                    mma_tf32(acc[mt][nt], reinterpret_cast<const uint32_t*>(&af[mt]),
                             reinterpret_cast<const uint32_t*>(&bf[nt]));
        }
        if (kt + 1 < ntiles) {
            sts_tile(cur ^ 1);
            __syncthreads();
            cur ^= 1;
        }
    }

#pragma unroll
    for (int mt = 0; mt < MT; mt++) {
#pragma unroll
        for (int nt = 0; nt < NT; nt++) {
            int gc = col0 + wn + nt * 8 + t4 * 2;
            if (gc >= N) continue;
            float bias0 = bp ? bp[gc] : 0.f;
            float bias1 = bp ? bp[gc + 1] : 0.f;
#pragma unroll
            for (int h = 0; h < 2; h++) {
                int gr = row0 + wm + mt * 16 + g + h * 8;
                if (gr >= Ml) continue;
                float v0 = acc[mt][nt][2 * h + 0] + bias0;
                float v1 = acc[mt][nt][2 * h + 1] + bias1;
                if (act == 1)      { v0 = fmaxf(v0, 0.f); v1 = fmaxf(v1, 0.f); }
                else if (act == 2) { v0 = (v0 > 0.f) ? v0 : 0.01f * v0;
                                     v1 = (v1 > 0.f) ? v1 : 0.01f * v1; }
                else if (act == 3) { v0 = tanhf(v0); v1 = tanhf(v1); }
                if (gnoise) {
                    const float* np = &gnoise[(size_t)gseeds[gr] * 64 + gc];
                    v0 += np[0];
                    v1 += np[1];
                }
                if (halfOut)
                    reinterpret_cast<uint32_t*>(C)[(size_t)gr * (N >> 1) + (gc >> 1)] =
                        packh2(v0, v1);
                else
                    *reinterpret_cast<float2*>(&C[(size_t)gr * N + gc]) = make_float2(v0, v1);
            }
        }
    }
}

// ------------------------- launcher -------------------------
extern "C" void kernel_launch(void* const* d_in, const int* in_sizes, int n_in,
                              void* d_out, int out_size) {
    (void)in_sizes; (void)n_in; (void)out_size;
    const float* x     = (const float*)d_in[0];
    const int*   edges = (const int*)d_in[1];
    const int*   seeds = (const int*)d_in[2];
    const float* noise = (const float*)d_in[3];
    const float* V1    = (const float*)d_in[4];
    const float* C1    = (const float*)d_in[5];
    const float* V2    = (const float*)d_in[6];
    const float* C2    = (const float*)d_in[7];
    const float* W_lin = (const float*)d_in[8];
    const float* b_lin = (const float*)d_in[9];
    const float* Wd1   = (const float*)d_in[10];
    const float* bd1   = (const float*)d_in[11];
    const float* Wd2   = (const float*)d_in[12];
    const float* bd2   = (const float*)d_in[13];
    const float* Wd3   = (const float*)d_in[14];
    const float* bd3   = (const float*)d_in[15];
    const float* Wf1   = (const float*)d_in[16];
    const float* bf1   = (const float*)d_in[17];
    const float* Wf2   = (const float*)d_in[18];
    const float* bf2   = (const float*)d_in[19];
    const float* Wf3   = (const float*)d_in[20];
    const float* bf3   = (const float*)d_in[21];
    float* out = (float*)d_out;

    void *pDeg, *pIs, *pNeed, *pCnt, *pBcat, *pH1, *pSA, *pH2, *pHs, *pD1, *pD2, *pF1h, *pF2h;
    cudaGetSymbolAddress(&pDeg, g_deg);
    cudaGetSymbolAddress(&pIs, g_isseed);
    cudaGetSymbolAddress(&pNeed, g_need);
    cudaGetSymbolAddress(&pCnt, g_cnt);
    cudaGetSymbolAddress(&pBcat, g_Bcat);
    cudaGetSymbolAddress(&pH1, g_h1h);
    cudaGetSymbolAddress(&pSA, g_sA);
    cudaGetSymbolAddress(&pH2, g_h2);
    cudaGetSymbolAddress(&pHs, g_hs);
    cudaGetSymbolAddress(&pD1, g_D1);
    cudaGetSymbolAddress(&pD2, g_D2);
    cudaGetSymbolAddress(&pF1h, g_F1h);
    cudaGetSymbolAddress(&pF2h, g_F2h);
    float* dBcat = (float*)pBcat;
    float* dH1   = (float*)pH1;      // __half storage; halfOut path
    float* dSA   = (float*)pSA;
    float* dH2   = (float*)pH2;
    float* dHs   = (float*)pHs;
    float* dD1   = (float*)pD1;
    float* dD2   = (float*)pD2;
    const int* dNcnt = ((const int*)pCnt) + 4;

    // one auxiliary stream + events for capture fork/join (created once; identical every call)
    static cudaStream_t s1 = nullptr;
    static cudaEvent_t evA, evAj, evB, evBj, evC, evCj;
    if (!s1) {
        cudaStreamCreateWithFlags(&s1, cudaStreamNonBlocking);
        cudaEventCreateWithFlags(&evA,  cudaEventDisableTiming);
        cudaEventCreateWithFlags(&evAj, cudaEventDisableTiming);
        cudaEventCreateWithFlags(&evB,  cudaEventDisableTiming);
        cudaEventCreateWithFlags(&evBj, cudaEventDisableTiming);
        cudaEventCreateWithFlags(&evC,  cudaEventDisableTiming);
        cudaEventCreateWithFlags(&evCj, cudaEventDisableTiming);
    }

    cudaMemsetAsync(pDeg, 0, sizeof(float) * RR * NN);
    cudaMemsetAsync(pIs, 0, NN);
    cudaMemsetAsync(pNeed, 0, NN);
    cudaMemsetAsync(pCnt, 0, sizeof(int) * 8);

    const int scatterBlocks = ((RR * EE / 2) * 8 + 255) / 256;

    // ---- fork A: x2h on aux stream, overlapping the edge-pass chain ----
    cudaEventRecord(evA, 0);
    cudaStreamWaitEvent(s1, evA, 0);
    k_x2h<<<(NN * 8 + 255) / 256, 256, 0, s1>>>(x);
    cudaEventRecord(evAj, s1);

    k_seedflag<<<(SS + 255) / 256, 256>>>(seeds);
    k_edgepass<<<(RR * EE + 255) / 256, 256>>>(edges);
    k_nodecount<<<(NN + 255) / 256, 256>>>();
    k_zeroA<<<1024, 256>>>();
    cudaStreamWaitEvent(0, evAj, 0);           // g_xh ready
    k_scatterA<<<scatterBlocks, 256>>>(edges);
    k_combine1<<<512, 256>>>(C1);

    // ---- fork B: zeroAseed overlapping gemm1 (both depend on combine1; disjoint buffers) ----
    cudaEventRecord(evB, 0);
    cudaStreamWaitEvent(s1, evB, 0);
    k_zeroAseed<<<(SS * RR * 8 + 255) / 256, 256, 0, s1>>>(seeds);
    cudaEventRecord(evBj, s1);

    mma_gemm<64, 32, 32, 1><<<dim3(1, (NN + 127) / 128, 1), 256>>>(
        dBcat, 0, V1, 0, nullptr, 0, 0, dH1, 0, NN, 64, 128, 1, nullptr, nullptr, dNcnt, 1);

    cudaStreamWaitEvent(0, evBj, 0);           // Ah seed rows zeroed
    k_scatterList<<<1024, 256>>>();
    k_combine2<<<(SS * 8 + 255) / 256, 256>>>(C2, seeds);
    mma_gemm<64, 32, 32, 1><<<dim3(1, SS / 128, 1), 256>>>(
        dSA, 0, V2, 0, nullptr, 0, 0, dH2, 0, SS, 64, 128, 1, nullptr, nullptr, nullptr, 0);

    // ---- linear + leaky + noise at seeds (noise fused into epilogue) ----
    mma_gemm<64, 32, 32, 1><<<dim3(1, SS / 128, 1), 256>>>(
        dH2, 0, W_lin, 0, b_lin, 0, 1, dHs, 0, SS, 64, 64, 2, noise, seeds, nullptr, 0);

    // ---- fork C: entire d branch on aux stream, overlapping the f branch ----
    cudaEventRecord(evC, 0);
    cudaStreamWaitEvent(s1, evC, 0);
    mma_gemm<128, 64, 32, 1><<<dim3(2, SS / 128, PP), 256, 0, s1>>>(
        dHs, 0, Wd1, (size_t)64 * 256, bd1, 256, 1, dD1, (size_t)SS * 256, SS, 256, 64, 2,
        nullptr, nullptr, nullptr, 0);
    mma_gemm<64, 32, 32, 1><<<dim3(1, SS / 128, PP), 256, 0, s1>>>(
        dD1, (size_t)SS * 256, Wd2, (size_t)256 * 32, bd2, 32, 1, dD2, (size_t)SS * 32,
        SS, 32, 256, 2, nullptr, nullptr, nullptr, 0);
    k_d3<<<(PP * SS + 255) / 256, 256, 0, s1>>>(Wd3, bd3, out);
    cudaEventRecord(evCj, s1);

    // ---- f branch on main stream (fp16 intermediates) ----
    mma_gemm<128, 64, 32, 1><<<dim3(2, SS / 128, PP), 256>>>(
        dHs, 0, Wf1, (size_t)64 * 256, bf1, 256, 1, (float*)pF1h, (size_t)SS * 128,
        SS, 256, 64, 1, nullptr, nullptr, nullptr, 1);
    hmma_gemm<128, 64, 64, 2><<<dim3(16, SS / 128, PP), 128>>>(
        (const __half*)pF1h, (size_t)SS * 256, Wf2, (size_t)256 * 2048, bf2, 2048,
        (float*)pF2h, (size_t)SS * 1024, SS, 2048, 256, 1, 1);
    hmma_gemm<128, 64, 64, 2><<<dim3(3, SS / 128, PP), 128>>>(
        (const __half*)pF2h, (size_t)SS * 2048, Wf3, (size_t)2048 * 320, bf3, 320,
        out + PP * SS, (size_t)SS * 320, SS, 320, 2048, 3, 0);

    // join d branch before returning (graph must have no dangling fork)
    cudaStreamWaitEvent(0, evCj, 0);
}

// round 16
// speedup vs baseline: 1.0352x; 1.0352x over previous
#include <cuda_runtime.h>
#include <cuda_fp16.h>
#include <cstdint>
#include <cstddef>

#define NN 100000
#define RR 4
#define EE 300000
#define HH 64
#define SS 4096
#define PP 2

// ------------------------- scratch (static device globals; no allocs) -------------------------
__device__ float g_deg[RR * NN];                 // raw degree counts (inverse taken inline)
__device__ __half g_xh[(size_t)NN * 64];         // x converted to fp16
__device__ __half g_Ah[(size_t)RR * NN * 64];    // per-relation aggregation, fp16
__device__ float g_Bcat[(size_t)NN * 128];       // combined [B0|B1], COMPACT rows (fp32)
__device__ __half g_h1h[(size_t)NN * HH];        // layer-1 output, COMPACT rows, fp16
__device__ unsigned char g_isseed[NN];
__device__ unsigned char g_need[NN];             // node is src of a seed-destined edge
__device__ int  g_nodes[NN];                     // compacted list of need-nodes
__device__ int  g_map[NN];                       // node -> compact index
__device__ int2 g_se[(size_t)RR * EE];           // compacted seed-destined edges per relation
__device__ int  g_cnt[8];                        // [0..3]=per-rel seed-edge count, [4]=need count
__device__ float g_sA[SS * 128];                 // combined layer-2 features at seeds (fp32)
__device__ float g_h2[SS * HH];
__device__ float g_hs[SS * HH];
__device__ float g_D1[PP * SS * 256];
__device__ float g_D2[PP * SS * 32];
__device__ float g_F1[PP * SS * 256];
__device__ float g_F2[(size_t)PP * SS * 2048];

// ------------------------- helpers -------------------------
__device__ __forceinline__ void red_add4h(__half* p, uint32_t a, uint32_t b,
                                          uint32_t c, uint32_t d) {
    asm volatile("red.global.add.noftz.v4.f16x2 [%0], {%1,%2,%3,%4};" ::
                 "l"(p), "r"(a), "r"(b), "r"(c), "r"(d) : "memory");
}

__device__ __forceinline__ uint32_t f2tf(float x) {
    uint32_t u;
    asm("cvt.rna.tf32.f32 %0, %1;" : "=r"(u) : "f"(x));
    return u;
}

__device__ __forceinline__ uint32_t packh2(float a, float b) {
    __half2 h = __floats2half2_rn(a, b);          // low half = a
    return *reinterpret_cast<uint32_t*>(&h);
}

__device__ __forceinline__ void mma_tf32(float* c, const uint32_t* a, const uint32_t* b) {
    asm volatile(
        "mma.sync.aligned.m16n8k8.row.col.f32.tf32.tf32.f32 "
        "{%0,%1,%2,%3},{%4,%5,%6,%7},{%8,%9},{%0,%1,%2,%3};"
        : "+f"(c[0]), "+f"(c[1]), "+f"(c[2]), "+f"(c[3])
        : "r"(a[0]), "r"(a[1]), "r"(a[2]), "r"(a[3]), "r"(b[0]), "r"(b[1]));
}

__device__ __forceinline__ void mma_f16(float* c, const uint32_t* a, const uint32_t* b) {
    asm volatile(
        "mma.sync.aligned.m16n8k16.row.col.f32.f16.f16.f32 "
        "{%0,%1,%2,%3},{%4,%5,%6,%7},{%8,%9},{%0,%1,%2,%3};"
        : "+f"(c[0]), "+f"(c[1]), "+f"(c[2]), "+f"(c[3])
        : "r"(a[0]), "r"(a[1]), "r"(a[2]), "r"(a[3]), "r"(b[0]), "r"(b[1]));
}

// ------------------------- small kernels -------------------------
__global__ void k_seedflag(const int* __restrict__ seeds) {
    int i = blockIdx.x * blockDim.x + threadIdx.x;
    if (i < SS) g_isseed[seeds[i]] = 1;
}

// convert x to fp16 (8 values per thread)
__global__ void k_x2h(const float* __restrict__ x) {
    int i = blockIdx.x * blockDim.x + threadIdx.x;
    if (i >= NN * 8) return;
    float4 a = *reinterpret_cast<const float4*>(&x[(size_t)i * 8]);
    float4 b = *reinterpret_cast<const float4*>(&x[(size_t)i * 8 + 4]);
    uint4 u = make_uint4(packh2(a.x, a.y), packh2(a.z, a.w),
                         packh2(b.x, b.y), packh2(b.z, b.w));
    *reinterpret_cast<uint4*>(&g_xh[(size_t)i * 8]) = u;
}

// single edge pass: degree + warp-aggregated compaction of seed-destined edges + need marks
__global__ void k_edgepass(const int* __restrict__ edges) {
    int e = blockIdx.x * blockDim.x + threadIdx.x;
    if (e >= RR * EE) return;
    int lane = threadIdx.x & 31;
    int r = e / EE;
    int2 ed = reinterpret_cast<const int2*>(edges)[e];
    atomicAdd(&g_deg[r * NN + ed.y], 1.0f);
    bool hit = g_isseed[ed.y] != 0;
    unsigned mask = __ballot_sync(0xffffffffu, hit);
    if (hit) {
        g_need[ed.x] = 1;
        int leader = __ffs(mask) - 1;
        int pos = 0;
        if (lane == leader) pos = atomicAdd(&g_cnt[r], __popc(mask));
        pos = __shfl_sync(mask, pos, leader);
        pos += __popc(mask & ((1u << lane) - 1u));
        g_se[(size_t)r * EE + pos] = ed;
    }
}

// warp-aggregated need-node compaction
__global__ void k_nodecount() {
    int n = blockIdx.x * blockDim.x + threadIdx.x;
    if (n >= NN) return;
    int lane = threadIdx.x & 31;
    bool need = g_need[n] != 0;
    unsigned mask = __ballot_sync(0xffffffffu, need);
    if (need) {
        int leader = __ffs(mask) - 1;
        int pos = 0;
        if (lane == leader) pos = atomicAdd(&g_cnt[4], __popc(mask));
        pos = __shfl_sync(mask, pos, leader);
        pos += __popc(mask & ((1u << lane) - 1u));
        g_nodes[pos] = n;
        g_map[n] = pos;
    }
}

// zero A rows of listed nodes (8 threads per node; 16B per (thread, r))
__global__ void k_zeroA() {
    int total = g_cnt[4] * 8;
    int stride = gridDim.x * blockDim.x;
    for (int t = blockIdx.x * blockDim.x + threadIdx.x; t < total; t += stride) {
        int e = t >> 3, i8 = t & 7;
        int n = g_nodes[e];
#pragma unroll
        for (int r = 0; r < RR; r++)
            *reinterpret_cast<uint4*>(&g_Ah[((size_t)r * NN + n) * 64 + i8 * 8]) =
                make_uint4(0u, 0u, 0u, 0u);
    }
}

// layer-1 scatter: A[r][dst] += xh[src] for needed dsts. 8 lanes/edge, 4 edges/thread (MLP).
__global__ void k_scatterA(const int* __restrict__ edges) {
    int gid = blockIdx.x * blockDim.x + threadIdx.x;
    int l = gid & 7;
    int e0 = (gid >> 3) * 4;
    if (e0 >= RR * EE) return;
    const int2* E = reinterpret_cast<const int2*>(edges);
    int2 ed[4];
    bool nd[4];
    uint4 xv[4];
#pragma unroll
    for (int j = 0; j < 4; j++) ed[j] = E[e0 + j];
#pragma unroll
    for (int j = 0; j < 4; j++) nd[j] = g_need[ed[j].y] != 0;
#pragma unroll
    for (int j = 0; j < 4; j++)
        xv[j] = nd[j] ? *reinterpret_cast<const uint4*>(&g_xh[(size_t)ed[j].x * 64 + l * 8])
                      : make_uint4(0u, 0u, 0u, 0u);
#pragma unroll
    for (int j = 0; j < 4; j++) {
        int r = (e0 + j) / EE;
        if (nd[j])
            red_add4h(&g_Ah[((size_t)r * NN + ed[j].y) * 64 + l * 8],
                      xv[j].x, xv[j].y, xv[j].z, xv[j].w);
    }
}

// layer-2 scatter over compacted seed-edge lists; h1h is COMPACT fp16 (row = g_map[node])
__global__ void k_scatterList() {
    int gid = blockIdx.x * blockDim.x + threadIdx.x;
    int l = gid & 7;
    int chunk = gid >> 3;
    int nchunks = (gridDim.x * blockDim.x) >> 3;
#pragma unroll
    for (int r = 0; r < RR; r++) {
        int c = g_cnt[r];
        for (int e = chunk; e < c; e += nchunks) {
            int2 ed = g_se[(size_t)r * EE + e];
            int hc = g_map[ed.x];
            uint4 xv = *reinterpret_cast<const uint4*>(&g_h1h[(size_t)hc * 64 + l * 8]);
            red_add4h(&g_Ah[((size_t)r * NN + ed.y) * 64 + l * 8], xv.x, xv.y, xv.z, xv.w);
        }
    }
}

// BcatC[e, b*64+i] = sum_r C[r,b]/max(deg,1) * Ah[r][n][i]  (8 threads per node)
__global__ void k_combine1(const float* __restrict__ Cmat) {
    int total = g_cnt[4] * 8;
    int stride = gridDim.x * blockDim.x;
    for (int t = blockIdx.x * blockDim.x + threadIdx.x; t < total; t += stride) {
        int e = t >> 3, i8 = t & 7;
        int n = g_nodes[e];
        float o0[8], o1[8];
#pragma unroll
        for (int j = 0; j < 8; j++) { o0[j] = 0.f; o1[j] = 0.f; }
#pragma unroll
        for (int r = 0; r < RR; r++) {
            float inv = 1.0f / fmaxf(__ldg(&g_deg[r * NN + n]), 1.0f);
            float c0 = __ldg(&Cmat[r * 2 + 0]) * inv;
            float c1 = __ldg(&Cmat[r * 2 + 1]) * inv;
            uint4 u = *reinterpret_cast<const uint4*>(&g_Ah[((size_t)r * NN + n) * 64 + i8 * 8]);
            const uint32_t uu[4] = {u.x, u.y, u.z, u.w};
#pragma unroll
            for (int q = 0; q < 4; q++) {
                float2 f = __half22float2(*reinterpret_cast<const __half2*>(&uu[q]));
                o0[2 * q + 0] += c0 * f.x; o0[2 * q + 1] += c0 * f.y;
                o1[2 * q + 0] += c1 * f.x; o1[2 * q + 1] += c1 * f.y;
            }
        }
        *reinterpret_cast<float4*>(&g_Bcat[(size_t)e * 128 + i8 * 8])      = *reinterpret_cast<float4*>(&o0[0]);
        *reinterpret_cast<float4*>(&g_Bcat[(size_t)e * 128 + i8 * 8 + 4])  = *reinterpret_cast<float4*>(&o0[4]);
        *reinterpret_cast<float4*>(&g_Bcat[(size_t)e * 128 + 64 + i8 * 8]) = *reinterpret_cast<float4*>(&o1[0]);
        *reinterpret_cast<float4*>(&g_Bcat[(size_t)e * 128 + 64 + i8 * 8 + 4]) = *reinterpret_cast<float4*>(&o1[4]);
    }
}

// zero A rows for seed nodes (8 threads per (seed, r))
__global__ void k_zeroAseed(const int* __restrict__ seeds) {
    int idx = blockIdx.x * blockDim.x + threadIdx.x;
    if (idx >= SS * RR * 8) return;
    int s = idx >> 5;
    int r = (idx >> 3) & 3;
    int i8 = idx & 7;
    int node = seeds[s];
    *reinterpret_cast<uint4*>(&g_Ah[((size_t)r * NN + node) * 64 + i8 * 8]) =
        make_uint4(0u, 0u, 0u, 0u);
}

// sA[s, b*64+i] = sum_r C2[r,b]/max(deg,1) * Ah[r][node][i]  (8 threads per seed)
__global__ void k_combine2(const float* __restrict__ Cmat, const int* __restrict__ seeds) {
    int idx = blockIdx.x * blockDim.x + threadIdx.x;
    if (idx >= SS * 8) return;
    int s = idx >> 3, i8 = idx & 7;
    int n = seeds[s];
    float o0[8], o1[8];
#pragma unroll
    for (int j = 0; j < 8; j++) { o0[j] = 0.f; o1[j] = 0.f; }
#pragma unroll
    for (int r = 0; r < RR; r++) {
        float inv = 1.0f / fmaxf(__ldg(&g_deg[r * NN + n]), 1.0f);
        float c0 = __ldg(&Cmat[r * 2 + 0]) * inv;
        float c1 = __ldg(&Cmat[r * 2 + 1]) * inv;
        uint4 u = *reinterpret_cast<const uint4*>(&g_Ah[((size_t)r * NN + n) * 64 + i8 * 8]);
        const uint32_t uu[4] = {u.x, u.y, u.z, u.w};
#pragma unroll
        for (int q = 0; q < 4; q++) {
            float2 f = __half22float2(*reinterpret_cast<const __half2*>(&uu[q]));
            o0[2 * q + 0] += c0 * f.x; o0[2 * q + 1] += c0 * f.y;
            o1[2 * q + 0] += c1 * f.x; o1[2 * q + 1] += c1 * f.y;
        }
    }
    *reinterpret_cast<float4*>(&g_sA[(size_t)s * 128 + i8 * 8])          = *reinterpret_cast<float4*>(&o0[0]);
    *reinterpret_cast<float4*>(&g_sA[(size_t)s * 128 + i8 * 8 + 4])      = *reinterpret_cast<float4*>(&o0[4]);
    *reinterpret_cast<float4*>(&g_sA[(size_t)s * 128 + 64 + i8 * 8])     = *reinterpret_cast<float4*>(&o1[0]);
    *reinterpret_cast<float4*>(&g_sA[(size_t)s * 128 + 64 + i8 * 8 + 4]) = *reinterpret_cast<float4*>(&o1[4]);
}

__global__ void k_d3(const float* __restrict__ Wd3, const float* __restrict__ bd3,
                     float* __restrict__ out) {
    int i = blockIdx.x * blockDim.x + threadIdx.x;
    if (i >= PP * SS) return;
    int p = i / SS;
    const float* v = &g_D2[(size_t)i * 32];
    const float* w = &Wd3[p * 32];
    float sum = bd3[p];
#pragma unroll
    for (int k = 0; k < 32; k++) sum += v[k] * w[k];
    out[i] = fmaxf(sum, 0.0f);
}

// ------------------------- fp16 tensor-core GEMM (big f-branch layers) -------------------------
template <int BN, int WM, int WN, int MINB>
__global__ __launch_bounds__(32 * (128 / WM) * (BN / WN), MINB)
void hmma_gemm(const float* __restrict__ A, size_t strA,
               const float* __restrict__ W, size_t strW,
               const float* __restrict__ bias, size_t strBias,
               float* __restrict__ C, size_t strC,
               int M, int N, int K, int act) {
    constexpr int BM = 128, BK = 32;
    constexpr int MT = WM / 16, NT = WN / 8;
    constexpr int WARPS_M = BM / WM;
    constexpr int NTH = 32 * WARPS_M * (BN / WN);
    constexpr int AGRP = 132;
    constexpr int BGRP = 68;
    constexpr int AWORDS = (BM / 16) * (BK / 16) * AGRP;
    constexpr int BWORDS = (BK / 16) * (BN / 8) * BGRP;
    constexpr int A4 = BM * BK / 4 / NTH;
    constexpr int BU = (BK / 2) * (BN / 4) / NTH;

    __shared__ uint32_t As[2][AWORDS];
    __shared__ uint32_t Bs[2][BWORDS];

    int tid = threadIdx.x, lane = tid & 31, wid = tid >> 5;
    int g = lane >> 2, t4 = lane & 3;
    int wm = (wid % WARPS_M) * WM;
    int wn = (wid / WARPS_M) * WN;

    int p = blockIdx.z;
    A    += (size_t)p * strA;
    W    += (size_t)p * strW;
    C    += (size_t)p * strC;
    const float* bp = bias + (size_t)p * strBias;

    int row0 = blockIdx.y * BM, col0 = blockIdx.x * BN;

    float acc[MT][NT][4];
#pragma unroll
    for (int mt = 0; mt < MT; mt++)
#pragma unroll
        for (int nt = 0; nt < NT; nt++)
#pragma unroll
            for (int i = 0; i < 4; i++) acc[mt][nt][i] = 0.f;

    float4 va[A4], vb0[BU], vb1[BU];

    auto ldg_tile = [&](int kt) {
#pragma unroll
        for (int i = 0; i < A4; i++) {
            int idx = tid + i * NTH;
            int r = idx >> 3;
            int c4 = (idx & 7) * 4;
            int gr = row0 + r;
            va[i] = (gr < M) ? *reinterpret_cast<const float4*>(&A[(size_t)gr * K + kt + c4])
                             : make_float4(0.f, 0.f, 0.f, 0.f);
        }
#pragma unroll
        for (int u = 0; u < BU; u++) {
            int uidx = tid + u * NTH;
            int kp = uidx / (BN / 4);
            int c4 = (uidx % (BN / 4)) * 4;
            int gc = col0 + c4;
            if (gc < N) {
                vb0[u] = *reinterpret_cast<const float4*>(&W[(size_t)(kt + 2 * kp) * N + gc]);
                vb1[u] = *reinterpret_cast<const float4*>(&W[(size_t)(kt + 2 * kp + 1) * N + gc]);
            } else {
                vb0[u] = make_float4(0.f, 0.f, 0.f, 0.f);
                vb1[u] = vb0[u];
            }
        }
    };
    auto sts_tile = [&](int buf) {
#pragma unroll
        for (int i = 0; i < A4; i++) {
            int idx = tid + i * NTH;
            int r = idx >> 3;
            int c4 = (idx & 7) * 4;
            int grp = (r >> 4) * (BK / 16) + (c4 >> 4);
            int k2p = (c4 >> 1) & 7;
            int reg = ((r >> 3) & 1) + (((k2p >> 2) & 1) << 1);
            int base = grp * AGRP + ((r & 7) * 4 + (k2p & 3)) * 4 + reg;
            As[buf][base]     = packh2(va[i].x, va[i].y);
            As[buf][base + 4] = packh2(va[i].z, va[i].w);
        }
#pragma unroll
        for (int u = 0; u < BU; u++) {
            int uidx = tid + u * NTH;
            int kp = uidx / (BN / 4);
            int c4 = (uidx % (BN / 4)) * 4;
            int k2p = kp & 7;
            int reg = (k2p >> 2) & 1;
            float w0[4] = {vb0[u].x, vb0[u].y, vb0[u].z, vb0[u].w};
            float w1[4] = {vb1[u].x, vb1[u].y, vb1[u].z, vb1[u].w};
#pragma unroll
            for (int j = 0; j < 4; j++) {
                int c = c4 + j;
                int grp = (kp >> 3) * (BN / 8) + (c >> 3);
                int off = grp * BGRP + ((c & 7) * 4 + (k2p & 3)) * 2 + reg;
                Bs[buf][off] = packh2(w0[j], w1[j]);
            }
        }
    };

    int ntiles = K / BK;
    ldg_tile(0);
    sts_tile(0);
    __syncthreads();
    int cur = 0;

    for (int kt = 0; kt < ntiles; kt++) {
        if (kt + 1 < ntiles) ldg_tile((kt + 1) * BK);
#pragma unroll
        for (int ksb = 0; ksb < BK / 16; ksb++) {
            uint4 af[MT];
            uint2 bf[NT];
#pragma unroll
            for (int mt = 0; mt < MT; mt++)
                af[mt] = *reinterpret_cast<const uint4*>(
                    &As[cur][(((wm >> 4) + mt) * (BK / 16) + ksb) * AGRP + lane * 4]);
#pragma unroll
            for (int nt = 0; nt < NT; nt++)
                bf[nt] = *reinterpret_cast<const uint2*>(
                    &Bs[cur][(ksb * (BN / 8) + (wn >> 3) + nt) * BGRP + lane * 2]);
#pragma unroll
            for (int mt = 0; mt < MT; mt++)
#pragma unroll
                for (int nt = 0; nt < NT; nt++)
                    mma_f16(acc[mt][nt], reinterpret_cast<const uint32_t*>(&af[mt]),
                            reinterpret_cast<const uint32_t*>(&bf[nt]));
        }
        if (kt + 1 < ntiles) {
            sts_tile(cur ^ 1);
            __syncthreads();
            cur ^= 1;
        }
    }

#pragma unroll
    for (int mt = 0; mt < MT; mt++) {
#pragma unroll
        for (int nt = 0; nt < NT; nt++) {
            int gc = col0 + wn + nt * 8 + t4 * 2;
            if (gc >= N) continue;
            float bias0 = bp[gc];
            float bias1 = bp[gc + 1];
#pragma unroll
            for (int h = 0; h < 2; h++) {
                int gr = row0 + wm + mt * 16 + g + h * 8;
                if (gr >= M) continue;
                float v0 = acc[mt][nt][2 * h + 0] + bias0;
                float v1 = acc[mt][nt][2 * h + 1] + bias1;
                if (act == 1) { v0 = fmaxf(v0, 0.f); v1 = fmaxf(v1, 0.f); }
                else          { v0 = tanhf(v0); v1 = tanhf(v1); }
                *reinterpret_cast<float2*>(&C[(size_t)gr * N + gc]) = make_float2(v0, v1);
            }
        }
    }
}

// ------------------------- tf32 mma.sync GEMM (small/medium layers) -------------------------
// halfOut != 0: C is a __half buffer (pitch N halfs); packed half2 stores.
template <int BN, int WM, int WN, int MINB>
__global__ __launch_bounds__(32 * (128 / WM) * (BN / WN), MINB)
void mma_gemm(const float* __restrict__ A, size_t strA,
              const float* __restrict__ W, size_t strW,
              const float* __restrict__ bias, size_t strBias, int hasBias,
              float* __restrict__ C, size_t strC,
              int M, int N, int K, int act,
              const float* __restrict__ gnoise, const int* __restrict__ gseeds,
              const int* __restrict__ Mdev, int halfOut) {
    constexpr int BM = 128, BK = 16;
    constexpr int MT = WM / 16, NT = WN / 8;
    constexpr int WARPS_M = BM / WM;
    constexpr int NTH = 32 * WARPS_M * (BN / WN);
    constexpr int AGRP = 132;
    constexpr int BGRP = 68;
    constexpr int AWORDS = (BM / 16) * (BK / 8) * AGRP;
    constexpr int BWORDS = (BK / 8) * (BN / 8) * BGRP;
    constexpr int A4 = BM * BK / 4 / NTH;
    constexpr int B4 = BK * BN / 4 / NTH;

    __shared__ uint32_t As[2][AWORDS];
    __shared__ uint32_t Bs[2][BWORDS];

    int tid = threadIdx.x, lane = tid & 31, wid = tid >> 5;
    int g = lane >> 2, t4 = lane & 3;
    int wm = (wid % WARPS_M) * WM;
    int wn = (wid / WARPS_M) * WN;

    int p = blockIdx.z;
    A += (size_t)p * strA;
    W += (size_t)p * strW;
    C += (size_t)p * strC;
    const float* bp = hasBias ? (bias + (size_t)p * strBias) : nullptr;

    int row0 = blockIdx.y * BM, col0 = blockIdx.x * BN;

    int Ml = M;
    if (Mdev) {
        Ml = *Mdev;
        if (row0 >= Ml) return;
    }

    float acc[MT][NT][4];
#pragma unroll
    for (int mt = 0; mt < MT; mt++)
#pragma unroll
        for (int nt = 0; nt < NT; nt++)
#pragma unroll
            for (int i = 0; i < 4; i++) acc[mt][nt][i] = 0.f;

    float4 va[A4], vb[B4];

    auto ldg_tile = [&](int kt) {
#pragma unroll
        for (int i = 0; i < A4; i++) {
            int idx = tid + i * NTH;
            int r = idx >> 2;
            int c4 = (idx & 3) * 4;
            int gr = row0 + r;
            va[i] = (gr < Ml) ? *reinterpret_cast<const float4*>(&A[(size_t)gr * K + kt + c4])
                              : make_float4(0.f, 0.f, 0.f, 0.f);
        }
#pragma unroll
        for (int i = 0; i < B4; i++) {
            int idx = tid + i * NTH;
            int r = idx / (BN / 4);
            int c4 = (idx % (BN / 4)) * 4;
            int gc = col0 + c4;
            vb[i] = (gc < N) ? *reinterpret_cast<const float4*>(&W[(size_t)(kt + r) * N + gc])
                             : make_float4(0.f, 0.f, 0.f, 0.f);
        }
    };
    auto sts_tile = [&](int buf) {
#pragma unroll
        for (int i = 0; i < A4; i++) {
            int idx = tid + i * NTH;
            int r = idx >> 2;
            int c4 = (idx & 3) * 4;
            int grp = ((r >> 4) * (BK / 8) + (c4 >> 3)) * AGRP;
            int reg = ((r >> 3) & 1) + (((c4 >> 2) & 1) << 1);
            int gg = r & 7;
            float f[4] = {va[i].x, va[i].y, va[i].z, va[i].w};
#pragma unroll
            for (int j = 0; j < 4; j++)
                As[buf][grp + (gg * 4 + j) * 4 + reg] = f2tf(f[j]);
        }
#pragma unroll
        for (int i = 0; i < B4; i++) {
            int idx = tid + i * NTH;
            int k = idx / (BN / 4);
            int c4 = (idx % (BN / 4)) * 4;
            int grp = ((k >> 3) * (BN / 8) + (c4 >> 3)) * BGRP;
            int reg = (k >> 2) & 1;
            int tt = k & 3;
            float f[4] = {vb[i].x, vb[i].y, vb[i].z, vb[i].w};
#pragma unroll
            for (int j = 0; j < 4; j++)
                Bs[buf][grp + (((c4 & 7) + j) * 4 + tt) * 2 + reg] = f2tf(f[j]);
        }
    };

    int ntiles = K / BK;
    ldg_tile(0);
    sts_tile(0);
    __syncthreads();
    int cur = 0;

    for (int kt = 0; kt < ntiles; kt++) {
        if (kt + 1 < ntiles) ldg_tile((kt + 1) * BK);
#pragma unroll
        for (int ksb = 0; ksb < BK / 8; ksb++) {
            uint4 af[MT];
            uint2 bf[NT];
#pragma unroll
            for (int mt = 0; mt < MT; mt++)
                af[mt] = *reinterpret_cast<const uint4*>(
                    &As[cur][(((wm >> 4) + mt) * (BK / 8) + ksb) * AGRP + lane * 4]);
#pragma unroll
            for (int nt = 0; nt < NT; nt++)
                bf[nt] = *reinterpret_cast<const uint2*>(
                    &Bs[cur][(ksb * (BN / 8) + (wn >> 3) + nt) * BGRP + lane * 2]);
#pragma unroll
            for (int mt = 0; mt < MT; mt++)
#pragma unroll
                for (int nt = 0; nt < NT; nt++)
                    mma_tf32(acc[mt][nt], reinterpret_cast<const uint32_t*>(&af[mt]),
                             reinterpret_cast<const uint32_t*>(&bf[nt]));
        }
        if (kt + 1 < ntiles) {
            sts_tile(cur ^ 1);
            __syncthreads();
            cur ^= 1;
        }
    }

#pragma unroll
    for (int mt = 0; mt < MT; mt++) {
#pragma unroll
        for (int nt = 0; nt < NT; nt++) {
            int gc = col0 + wn + nt * 8 + t4 * 2;
            if (gc >= N) continue;
            float bias0 = bp ? bp[gc] : 0.f;
            float bias1 = bp ? bp[gc + 1] : 0.f;
#pragma unroll
            for (int h = 0; h < 2; h++) {
                int gr = row0 + wm + mt * 16 + g + h * 8;
                if (gr >= Ml) continue;
                float v0 = acc[mt][nt][2 * h + 0] + bias0;
                float v1 = acc[mt][nt][2 * h + 1] + bias1;
                if (act == 1)      { v0 = fmaxf(v0, 0.f); v1 = fmaxf(v1, 0.f); }
                else if (act == 2) { v0 = (v0 > 0.f) ? v0 : 0.01f * v0;
                                     v1 = (v1 > 0.f) ? v1 : 0.01f * v1; }
                else if (act == 3) { v0 = tanhf(v0); v1 = tanhf(v1); }
                if (gnoise) {
                    const float* np = &gnoise[(size_t)gseeds[gr] * 64 + gc];
                    v0 += np[0];
                    v1 += np[1];
                }
                if (halfOut)
                    reinterpret_cast<uint32_t*>(C)[(size_t)gr * (N >> 1) + (gc >> 1)] =
                        packh2(v0, v1);
                else
                    *reinterpret_cast<float2*>(&C[(size_t)gr * N + gc]) = make_float2(v0, v1);
            }
        }
    }
}

// ------------------------- launcher -------------------------
extern "C" void kernel_launch(void* const* d_in, const int* in_sizes, int n_in,
                              void* d_out, int out_size) {
    (void)in_sizes; (void)n_in; (void)out_size;
    const float* x     = (const float*)d_in[0];
    const int*   edges = (const int*)d_in[1];
    const int*   seeds = (const int*)d_in[2];
    const float* noise = (const float*)d_in[3];
    const float* V1    = (const float*)d_in[4];
    const float* C1    = (const float*)d_in[5];
    const float* V2    = (const float*)d_in[6];
    const float* C2    = (const float*)d_in[7];
    const float* W_lin = (const float*)d_in[8];
    const float* b_lin = (const float*)d_in[9];
    const float* Wd1   = (const float*)d_in[10];
    const float* bd1   = (const float*)d_in[11];
    const float* Wd2   = (const float*)d_in[12];
    const float* bd2   = (const float*)d_in[13];
    const float* Wd3   = (const float*)d_in[14];
    const float* bd3   = (const float*)d_in[15];
    const float* Wf1   = (const float*)d_in[16];
    const float* bf1   = (const float*)d_in[17];
    const float* Wf2   = (const float*)d_in[18];
    const float* bf2   = (const float*)d_in[19];
    const float* Wf3   = (const float*)d_in[20];
    const float* bf3   = (const float*)d_in[21];
    float* out = (float*)d_out;

    void *pDeg, *pIs, *pNeed, *pCnt, *pBcat, *pH1, *pSA, *pH2, *pHs, *pD1, *pD2, *pF1, *pF2;
    cudaGetSymbolAddress(&pDeg, g_deg);
    cudaGetSymbolAddress(&pIs, g_isseed);
    cudaGetSymbolAddress(&pNeed, g_need);
    cudaGetSymbolAddress(&pCnt, g_cnt);
    cudaGetSymbolAddress(&pBcat, g_Bcat);
    cudaGetSymbolAddress(&pH1, g_h1h);
    cudaGetSymbolAddress(&pSA, g_sA);
    cudaGetSymbolAddress(&pH2, g_h2);
    cudaGetSymbolAddress(&pHs, g_hs);
    cudaGetSymbolAddress(&pD1, g_D1);
    cudaGetSymbolAddress(&pD2, g_D2);
    cudaGetSymbolAddress(&pF1, g_F1);
    cudaGetSymbolAddress(&pF2, g_F2);
    float* dBcat = (float*)pBcat;
    float* dH1   = (float*)pH1;      // __half storage; halfOut path
    float* dSA   = (float*)pSA;
    float* dH2   = (float*)pH2;
    float* dHs   = (float*)pHs;
    float* dD1   = (float*)pD1;
    float* dD2   = (float*)pD2;
    float* dF1   = (float*)pF1;
    float* dF2   = (float*)pF2;
    const int* dNcnt = ((const int*)pCnt) + 4;

    // one auxiliary stream + events for capture fork/join (created once; identical every call)
    static cudaStream_t s1 = nullptr;
    static cudaEvent_t evA, evAj, evB, evBj, evC, evCj;
    if (!s1) {
        cudaStreamCreateWithFlags(&s1, cudaStreamNonBlocking);
        cudaEventCreateWithFlags(&evA,  cudaEventDisableTiming);
        cudaEventCreateWithFlags(&evAj, cudaEventDisableTiming);
        cudaEventCreateWithFlags(&evB,  cudaEventDisableTiming);
        cudaEventCreateWithFlags(&evBj, cudaEventDisableTiming);
        cudaEventCreateWithFlags(&evC,  cudaEventDisableTiming);
        cudaEventCreateWithFlags(&evCj, cudaEventDisableTiming);
    }

    cudaMemsetAsync(pDeg, 0, sizeof(float) * RR * NN);
    cudaMemsetAsync(pIs, 0, NN);
    cudaMemsetAsync(pNeed, 0, NN);
    cudaMemsetAsync(pCnt, 0, sizeof(int) * 8);

    const int scatterBlocks = ((RR * EE / 4) * 8 + 255) / 256;

    // ---- fork A: x2h on aux stream, overlapping the edge-pass chain ----
    cudaEventRecord(evA, 0);
    cudaStreamWaitEvent(s1, evA, 0);
    k_x2h<<<(NN * 8 + 255) / 256, 256, 0, s1>>>(x);
    cudaEventRecord(evAj, s1);

    k_seedflag<<<(SS + 255) / 256, 256>>>(seeds);
    k_edgepass<<<(RR * EE + 255) / 256, 256>>>(edges);
    k_nodecount<<<(NN + 255) / 256, 256>>>();
    k_zeroA<<<1024, 256>>>();
    cudaStreamWaitEvent(0, evAj, 0);           // g_xh ready
    k_scatterA<<<scatterBlocks, 256>>>(edges);
    k_combine1<<<512, 256>>>(C1);

    // ---- fork B: zeroAseed overlapping gemm1 (both depend on combine1; disjoint buffers) ----
    cudaEventRecord(evB, 0);
    cudaStreamWaitEvent(s1, evB, 0);
    k_zeroAseed<<<(SS * RR * 8 + 255) / 256, 256, 0, s1>>>(seeds);
    cudaEventRecord(evBj, s1);

    mma_gemm<64, 32, 32, 1><<<dim3(1, (NN + 127) / 128, 1), 256>>>(
        dBcat, 0, V1, 0, nullptr, 0, 0, dH1, 0, NN, 64, 128, 1, nullptr, nullptr, dNcnt, 1);

    cudaStreamWaitEvent(0, evBj, 0);           // Ah seed rows zeroed
    k_scatterList<<<1024, 256>>>();
    k_combine2<<<(SS * 8 + 255) / 256, 256>>>(C2, seeds);
    mma_gemm<64, 32, 32, 1><<<dim3(1, SS / 128, 1), 256>>>(
        dSA, 0, V2, 0, nullptr, 0, 0, dH2, 0, SS, 64, 128, 1, nullptr, nullptr, nullptr, 0);

    // ---- linear + leaky + noise at seeds (noise fused into epilogue) ----
    mma_gemm<64, 32, 32, 1><<<dim3(1, SS / 128, 1), 256>>>(
        dH2, 0, W_lin, 0, b_lin, 0, 1, dHs, 0, SS, 64, 64, 2, noise, seeds, nullptr, 0);

    // ---- fork C: entire d branch on aux stream, overlapping the f branch ----
    cudaEventRecord(evC, 0);
    cudaStreamWaitEvent(s1, evC, 0);
    mma_gemm<128, 64, 32, 1><<<dim3(2, SS / 128, PP), 256, 0, s1>>>(
        dHs, 0, Wd1, (size_t)64 * 256, bd1, 256, 1, dD1, (size_t)SS * 256, SS, 256, 64, 2,
        nullptr, nullptr, nullptr, 0);
    mma_gemm<64, 32, 32, 1><<<dim3(1, SS / 128, PP), 256, 0, s1>>>(
        dD1, (size_t)SS * 256, Wd2, (size_t)256 * 32, bd2, 32, 1, dD2, (size_t)SS * 32,
        SS, 32, 256, 2, nullptr, nullptr, nullptr, 0);
    k_d3<<<(PP * SS + 255) / 256, 256, 0, s1>>>(Wd3, bd3, out);
    cudaEventRecord(evCj, s1);

    // ---- f branch on main stream ----
    mma_gemm<128, 64, 32, 1><<<dim3(2, SS / 128, PP), 256>>>(
        dHs, 0, Wf1, (size_t)64 * 256, bf1, 256, 1, dF1, (size_t)SS * 256, SS, 256, 64, 1,
        nullptr, nullptr, nullptr, 0);
    hmma_gemm<128, 64, 64, 2><<<dim3(16, SS / 128, PP), 128>>>(
        dF1, (size_t)SS * 256, Wf2, (size_t)256 * 2048, bf2, 2048,
        dF2, (size_t)SS * 2048, SS, 2048, 256, 1);
    hmma_gemm<128, 64, 64, 2><<<dim3(3, SS / 128, PP), 128>>>(
        dF2, (size_t)SS * 2048, Wf3, (size_t)2048 * 320, bf3, 320,
        out + PP * SS, (size_t)SS * 320, SS, 320, 2048, 3);

    // join d branch before returning (graph must have no dangling fork)
    cudaStreamWaitEvent(0, evCj, 0);
}

// round 17
// speedup vs baseline: 1.0434x; 1.0079x over previous
#include <cuda_runtime.h>
#include <cuda_fp16.h>
#include <cstdint>
#include <cstddef>

#define NN 100000
#define RR 4
#define EE 300000
#define HH 64
#define SS 4096
#define PP 2

// ------------------------- scratch (static device globals; no allocs) -------------------------
__device__ float g_deg[RR * NN];                 // raw degree counts (inverse taken inline)
__device__ __half g_xh[(size_t)NN * 64];         // x converted to fp16
__device__ __half g_Ah[(size_t)RR * NN * 64];    // per-relation aggregation, fp16
__device__ float g_Bcat[(size_t)NN * 128];       // combined [B0|B1], COMPACT rows (fp32)
__device__ __half g_h1h[(size_t)NN * HH];        // layer-1 output, COMPACT rows, fp16
__device__ unsigned char g_isseed[NN];
__device__ unsigned char g_need[NN];             // node is src of a seed-destined edge
__device__ int  g_nodes[NN];                     // compacted list of need-nodes
__device__ int  g_map[NN];                       // node -> compact index
__device__ int2 g_se[(size_t)RR * EE];           // compacted seed-destined edges per relation
__device__ int  g_cnt[8];                        // [0..3]=per-rel seed-edge count, [4]=need count
__device__ float g_sA[SS * 128];                 // combined layer-2 features at seeds (fp32)
__device__ float g_h2[SS * HH];
__device__ float g_hs[SS * HH];
__device__ float g_D1[PP * SS * 256];
__device__ float g_D2[PP * SS * 32];
__device__ float g_F1[PP * SS * 256];
__device__ float g_F2[(size_t)PP * SS * 2048];

// ------------------------- helpers -------------------------
__device__ __forceinline__ void red_add4h(__half* p, uint32_t a, uint32_t b,
                                          uint32_t c, uint32_t d) {
    asm volatile("red.global.add.noftz.v4.f16x2 [%0], {%1,%2,%3,%4};" ::
                 "l"(p), "r"(a), "r"(b), "r"(c), "r"(d) : "memory");
}

__device__ __forceinline__ uint32_t f2tf(float x) {
    uint32_t u;
    asm("cvt.rna.tf32.f32 %0, %1;" : "=r"(u) : "f"(x));
    return u;
}

__device__ __forceinline__ uint32_t packh2(float a, float b) {
    __half2 h = __floats2half2_rn(a, b);          // low half = a
    return *reinterpret_cast<uint32_t*>(&h);
}

__device__ __forceinline__ void mma_tf32(float* c, const uint32_t* a, const uint32_t* b) {
    asm volatile(
        "mma.sync.aligned.m16n8k8.row.col.f32.tf32.tf32.f32 "
        "{%0,%1,%2,%3},{%4,%5,%6,%7},{%8,%9},{%0,%1,%2,%3};"
        : "+f"(c[0]), "+f"(c[1]), "+f"(c[2]), "+f"(c[3])
        : "r"(a[0]), "r"(a[1]), "r"(a[2]), "r"(a[3]), "r"(b[0]), "r"(b[1]));
}

__device__ __forceinline__ void mma_f16(float* c, const uint32_t* a, const uint32_t* b) {
    asm volatile(
        "mma.sync.aligned.m16n8k16.row.col.f32.f16.f16.f32 "
        "{%0,%1,%2,%3},{%4,%5,%6,%7},{%8,%9},{%0,%1,%2,%3};"
        : "+f"(c[0]), "+f"(c[1]), "+f"(c[2]), "+f"(c[3])
        : "r"(a[0]), "r"(a[1]), "r"(a[2]), "r"(a[3]), "r"(b[0]), "r"(b[1]));
}

// ------------------------- small kernels -------------------------
__global__ void k_seedflag(const int* __restrict__ seeds) {
    int i = blockIdx.x * blockDim.x + threadIdx.x;
    if (i < SS) g_isseed[seeds[i]] = 1;
}

// convert x to fp16 (8 values per thread)
__global__ void k_x2h(const float* __restrict__ x) {
    int i = blockIdx.x * blockDim.x + threadIdx.x;
    if (i >= NN * 8) return;
    float4 a = *reinterpret_cast<const float4*>(&x[(size_t)i * 8]);
    float4 b = *reinterpret_cast<const float4*>(&x[(size_t)i * 8 + 4]);
    uint4 u = make_uint4(packh2(a.x, a.y), packh2(a.z, a.w),
                         packh2(b.x, b.y), packh2(b.z, b.w));
    *reinterpret_cast<uint4*>(&g_xh[(size_t)i * 8]) = u;
}

// degree counting only (independent of seedflag; runs on aux stream)
__global__ void k_deg(const int* __restrict__ edges) {
    int e = blockIdx.x * blockDim.x + threadIdx.x;
    if (e >= RR * EE) return;
    int r = e / EE;
    int dst = edges[2 * e + 1];
    atomicAdd(&g_deg[r * NN + dst], 1.0f);
}

// edge compaction pass: warp-aggregated seed-destined edge lists + need marks
__global__ void k_edgepass(const int* __restrict__ edges) {
    int e = blockIdx.x * blockDim.x + threadIdx.x;
    if (e >= RR * EE) return;
    int lane = threadIdx.x & 31;
    int r = e / EE;
    int2 ed = reinterpret_cast<const int2*>(edges)[e];
    bool hit = g_isseed[ed.y] != 0;
    unsigned mask = __ballot_sync(0xffffffffu, hit);
    if (hit) {
        g_need[ed.x] = 1;
        int leader = __ffs(mask) - 1;
        int pos = 0;
        if (lane == leader) pos = atomicAdd(&g_cnt[r], __popc(mask));
        pos = __shfl_sync(mask, pos, leader);
        pos += __popc(mask & ((1u << lane) - 1u));
        g_se[(size_t)r * EE + pos] = ed;
    }
}

// warp-aggregated need-node compaction
__global__ void k_nodecount() {
    int n = blockIdx.x * blockDim.x + threadIdx.x;
    if (n >= NN) return;
    int lane = threadIdx.x & 31;
    bool need = g_need[n] != 0;
    unsigned mask = __ballot_sync(0xffffffffu, need);
    if (need) {
        int leader = __ffs(mask) - 1;
        int pos = 0;
        if (lane == leader) pos = atomicAdd(&g_cnt[4], __popc(mask));
        pos = __shfl_sync(mask, pos, leader);
        pos += __popc(mask & ((1u << lane) - 1u));
        g_nodes[pos] = n;
        g_map[n] = pos;
    }
}

// zero A rows of listed nodes (8 threads per node; 16B per (thread, r))
__global__ void k_zeroA() {
    int total = g_cnt[4] * 8;
    int stride = gridDim.x * blockDim.x;
    for (int t = blockIdx.x * blockDim.x + threadIdx.x; t < total; t += stride) {
        int e = t >> 3, i8 = t & 7;
        int n = g_nodes[e];
#pragma unroll
        for (int r = 0; r < RR; r++)
            *reinterpret_cast<uint4*>(&g_Ah[((size_t)r * NN + n) * 64 + i8 * 8]) =
                make_uint4(0u, 0u, 0u, 0u);
    }
}

// layer-1 scatter: A[r][dst] += xh[src] for needed dsts. 8 lanes/edge, 4 edges/thread (MLP).
__global__ void k_scatterA(const int* __restrict__ edges) {
    int gid = blockIdx.x * blockDim.x + threadIdx.x;
    int l = gid & 7;
    int e0 = (gid >> 3) * 4;
    if (e0 >= RR * EE) return;
    const int2* E = reinterpret_cast<const int2*>(edges);
    int2 ed[4];
    bool nd[4];
    uint4 xv[4];
#pragma unroll
    for (int j = 0; j < 4; j++) ed[j] = E[e0 + j];
#pragma unroll
    for (int j = 0; j < 4; j++) nd[j] = g_need[ed[j].y] != 0;
#pragma unroll
    for (int j = 0; j < 4; j++)
        xv[j] = nd[j] ? *reinterpret_cast<const uint4*>(&g_xh[(size_t)ed[j].x * 64 + l * 8])
                      : make_uint4(0u, 0u, 0u, 0u);
#pragma unroll
    for (int j = 0; j < 4; j++) {
        int r = (e0 + j) / EE;
        if (nd[j])
            red_add4h(&g_Ah[((size_t)r * NN + ed[j].y) * 64 + l * 8],
                      xv[j].x, xv[j].y, xv[j].z, xv[j].w);
    }
}

// layer-2 scatter over compacted seed-edge lists; h1h is COMPACT fp16 (row = g_map[node])
__global__ void k_scatterList() {
    int gid = blockIdx.x * blockDim.x + threadIdx.x;
    int l = gid & 7;
    int chunk = gid >> 3;
    int nchunks = (gridDim.x * blockDim.x) >> 3;
#pragma unroll
    for (int r = 0; r < RR; r++) {
        int c = g_cnt[r];
        for (int e = chunk; e < c; e += nchunks) {
            int2 ed = g_se[(size_t)r * EE + e];
            int hc = g_map[ed.x];
            uint4 xv = *reinterpret_cast<const uint4*>(&g_h1h[(size_t)hc * 64 + l * 8]);
            red_add4h(&g_Ah[((size_t)r * NN + ed.y) * 64 + l * 8], xv.x, xv.y, xv.z, xv.w);
        }
    }
}

// BcatC[e, b*64+i] = sum_r C[r,b]/max(deg,1) * Ah[r][n][i]  (8 threads per node)
__global__ void k_combine1(const float* __restrict__ Cmat) {
    int total = g_cnt[4] * 8;
    int stride = gridDim.x * blockDim.x;
    for (int t = blockIdx.x * blockDim.x + threadIdx.x; t < total; t += stride) {
        int e = t >> 3, i8 = t & 7;
        int n = g_nodes[e];
        float o0[8], o1[8];
#pragma unroll
        for (int j = 0; j < 8; j++) { o0[j] = 0.f; o1[j] = 0.f; }
#pragma unroll
        for (int r = 0; r < RR; r++) {
            float inv = 1.0f / fmaxf(__ldg(&g_deg[r * NN + n]), 1.0f);
            float c0 = __ldg(&Cmat[r * 2 + 0]) * inv;
            float c1 = __ldg(&Cmat[r * 2 + 1]) * inv;
            uint4 u = *reinterpret_cast<const uint4*>(&g_Ah[((size_t)r * NN + n) * 64 + i8 * 8]);
            const uint32_t uu[4] = {u.x, u.y, u.z, u.w};
#pragma unroll
            for (int q = 0; q < 4; q++) {
                float2 f = __half22float2(*reinterpret_cast<const __half2*>(&uu[q]));
                o0[2 * q + 0] += c0 * f.x; o0[2 * q + 1] += c0 * f.y;
                o1[2 * q + 0] += c1 * f.x; o1[2 * q + 1] += c1 * f.y;
            }
        }
        *reinterpret_cast<float4*>(&g_Bcat[(size_t)e * 128 + i8 * 8])      = *reinterpret_cast<float4*>(&o0[0]);
        *reinterpret_cast<float4*>(&g_Bcat[(size_t)e * 128 + i8 * 8 + 4])  = *reinterpret_cast<float4*>(&o0[4]);
        *reinterpret_cast<float4*>(&g_Bcat[(size_t)e * 128 + 64 + i8 * 8]) = *reinterpret_cast<float4*>(&o1[0]);
        *reinterpret_cast<float4*>(&g_Bcat[(size_t)e * 128 + 64 + i8 * 8 + 4]) = *reinterpret_cast<float4*>(&o1[4]);
    }
}

// zero A rows for seed nodes (8 threads per (seed, r))
__global__ void k_zeroAseed(const int* __restrict__ seeds) {
    int idx = blockIdx.x * blockDim.x + threadIdx.x;
    if (idx >= SS * RR * 8) return;
    int s = idx >> 5;
    int r = (idx >> 3) & 3;
    int i8 = idx & 7;
    int node = seeds[s];
    *reinterpret_cast<uint4*>(&g_Ah[((size_t)r * NN + node) * 64 + i8 * 8]) =
        make_uint4(0u, 0u, 0u, 0u);
}

// sA[s, b*64+i] = sum_r C2[r,b]/max(deg,1) * Ah[r][node][i]  (8 threads per seed)
__global__ void k_combine2(const float* __restrict__ Cmat, const int* __restrict__ seeds) {
    int idx = blockIdx.x * blockDim.x + threadIdx.x;
    if (idx >= SS * 8) return;
    int s = idx >> 3, i8 = idx & 7;
    int n = seeds[s];
    float o0[8], o1[8];
#pragma unroll
    for (int j = 0; j < 8; j++) { o0[j] = 0.f; o1[j] = 0.f; }
#pragma unroll
    for (int r = 0; r < RR; r++) {
        float inv = 1.0f / fmaxf(__ldg(&g_deg[r * NN + n]), 1.0f);
        float c0 = __ldg(&Cmat[r * 2 + 0]) * inv;
        float c1 = __ldg(&Cmat[r * 2 + 1]) * inv;
        uint4 u = *reinterpret_cast<const uint4*>(&g_Ah[((size_t)r * NN + n) * 64 + i8 * 8]);
        const uint32_t uu[4] = {u.x, u.y, u.z, u.w};
#pragma unroll
        for (int q = 0; q < 4; q++) {
            float2 f = __half22float2(*reinterpret_cast<const __half2*>(&uu[q]));
            o0[2 * q + 0] += c0 * f.x; o0[2 * q + 1] += c0 * f.y;
            o1[2 * q + 0] += c1 * f.x; o1[2 * q + 1] += c1 * f.y;
        }
    }
    *reinterpret_cast<float4*>(&g_sA[(size_t)s * 128 + i8 * 8])          = *reinterpret_cast<float4*>(&o0[0]);
    *reinterpret_cast<float4*>(&g_sA[(size_t)s * 128 + i8 * 8 + 4])      = *reinterpret_cast<float4*>(&o0[4]);
    *reinterpret_cast<float4*>(&g_sA[(size_t)s * 128 + 64 + i8 * 8])     = *reinterpret_cast<float4*>(&o1[0]);
    *reinterpret_cast<float4*>(&g_sA[(size_t)s * 128 + 64 + i8 * 8 + 4]) = *reinterpret_cast<float4*>(&o1[4]);
}

__global__ void k_d3(const float* __restrict__ Wd3, const float* __restrict__ bd3,
                     float* __restrict__ out) {
    int i = blockIdx.x * blockDim.x + threadIdx.x;
    if (i >= PP * SS) return;
    int p = i / SS;
    const float* v = &g_D2[(size_t)i * 32];
    const float* w = &Wd3[p * 32];
    float sum = bd3[p];
#pragma unroll
    for (int k = 0; k < 32; k++) sum += v[k] * w[k];
    out[i] = fmaxf(sum, 0.0f);
}

// ------------------------- fp16 tensor-core GEMM (big f-branch layers) -------------------------
template <int BN, int WM, int WN, int MINB>
__global__ __launch_bounds__(32 * (128 / WM) * (BN / WN), MINB)
void hmma_gemm(const float* __restrict__ A, size_t strA,
               const float* __restrict__ W, size_t strW,
               const float* __restrict__ bias, size_t strBias,
               float* __restrict__ C, size_t strC,
               int M, int N, int K, int act) {
    constexpr int BM = 128, BK = 32;
    constexpr int MT = WM / 16, NT = WN / 8;
    constexpr int WARPS_M = BM / WM;
    constexpr int NTH = 32 * WARPS_M * (BN / WN);
    constexpr int AGRP = 132;
    constexpr int BGRP = 68;
    constexpr int AWORDS = (BM / 16) * (BK / 16) * AGRP;
    constexpr int BWORDS = (BK / 16) * (BN / 8) * BGRP;
    constexpr int A4 = BM * BK / 4 / NTH;
    constexpr int BU = (BK / 2) * (BN / 4) / NTH;

    __shared__ uint32_t As[2][AWORDS];
    __shared__ uint32_t Bs[2][BWORDS];

    int tid = threadIdx.x, lane = tid & 31, wid = tid >> 5;
    int g = lane >> 2, t4 = lane & 3;
    int wm = (wid % WARPS_M) * WM;
    int wn = (wid / WARPS_M) * WN;

    int p = blockIdx.z;
    A    += (size_t)p * strA;
    W    += (size_t)p * strW;
    C    += (size_t)p * strC;
    const float* bp = bias + (size_t)p * strBias;

    int row0 = blockIdx.y * BM, col0 = blockIdx.x * BN;

    float acc[MT][NT][4];
#pragma unroll
    for (int mt = 0; mt < MT; mt++)
#pragma unroll
        for (int nt = 0; nt < NT; nt++)
#pragma unroll
            for (int i = 0; i < 4; i++) acc[mt][nt][i] = 0.f;

    float4 va[A4], vb0[BU], vb1[BU];

    auto ldg_tile = [&](int kt) {
#pragma unroll
        for (int i = 0; i < A4; i++) {
            int idx = tid + i * NTH;
            int r = idx >> 3;
            int c4 = (idx & 7) * 4;
            int gr = row0 + r;
            va[i] = (gr < M) ? *reinterpret_cast<const float4*>(&A[(size_t)gr * K + kt + c4])
                             : make_float4(0.f, 0.f, 0.f, 0.f);
        }
#pragma unroll
        for (int u = 0; u < BU; u++) {
            int uidx = tid + u * NTH;
            int kp = uidx / (BN / 4);
            int c4 = (uidx % (BN / 4)) * 4;
            int gc = col0 + c4;
            if (gc < N) {
                vb0[u] = *reinterpret_cast<const float4*>(&W[(size_t)(kt + 2 * kp) * N + gc]);
                vb1[u] = *reinterpret_cast<const float4*>(&W[(size_t)(kt + 2 * kp + 1) * N + gc]);
            } else {
                vb0[u] = make_float4(0.f, 0.f, 0.f, 0.f);
                vb1[u] = vb0[u];
            }
        }
    };
    auto sts_tile = [&](int buf) {
#pragma unroll
        for (int i = 0; i < A4; i++) {
            int idx = tid + i * NTH;
            int r = idx >> 3;
            int c4 = (idx & 7) * 4;
            int grp = (r >> 4) * (BK / 16) + (c4 >> 4);
            int k2p = (c4 >> 1) & 7;
            int reg = ((r >> 3) & 1) + (((k2p >> 2) & 1) << 1);
            int base = grp * AGRP + ((r & 7) * 4 + (k2p & 3)) * 4 + reg;
            As[buf][base]     = packh2(va[i].x, va[i].y);
            As[buf][base + 4] = packh2(va[i].z, va[i].w);
        }
#pragma unroll
        for (int u = 0; u < BU; u++) {
            int uidx = tid + u * NTH;
            int kp = uidx / (BN / 4);
            int c4 = (uidx % (BN / 4)) * 4;
            int k2p = kp & 7;
            int reg = (k2p >> 2) & 1;
            float w0[4] = {vb0[u].x, vb0[u].y, vb0[u].z, vb0[u].w};
            float w1[4] = {vb1[u].x, vb1[u].y, vb1[u].z, vb1[u].w};
#pragma unroll
            for (int j = 0; j < 4; j++) {
                int c = c4 + j;
                int grp = (kp >> 3) * (BN / 8) + (c >> 3);
                int off = grp * BGRP + ((c & 7) * 4 + (k2p & 3)) * 2 + reg;
                Bs[buf][off] = packh2(w0[j], w1[j]);
            }
        }
    };

    int ntiles = K / BK;
    ldg_tile(0);
    sts_tile(0);
    __syncthreads();
    int cur = 0;

    for (int kt = 0; kt < ntiles; kt++) {
        if (kt + 1 < ntiles) ldg_tile((kt + 1) * BK);
#pragma unroll
        for (int ksb = 0; ksb < BK / 16; ksb++) {
            uint4 af[MT];
            uint2 bf[NT];
#pragma unroll
            for (int mt = 0; mt < MT; mt++)
                af[mt] = *reinterpret_cast<const uint4*>(
                    &As[cur][(((wm >> 4) + mt) * (BK / 16) + ksb) * AGRP + lane * 4]);
#pragma unroll
            for (int nt = 0; nt < NT; nt++)
                bf[nt] = *reinterpret_cast<const uint2*>(
                    &Bs[cur][(ksb * (BN / 8) + (wn >> 3) + nt) * BGRP + lane * 2]);
#pragma unroll
            for (int mt = 0; mt < MT; mt++)
#pragma unroll
                for (int nt = 0; nt < NT; nt++)
                    mma_f16(acc[mt][nt], reinterpret_cast<const uint32_t*>(&af[mt]),
                            reinterpret_cast<const uint32_t*>(&bf[nt]));
        }
        if (kt + 1 < ntiles) {
            sts_tile(cur ^ 1);
            __syncthreads();
            cur ^= 1;
        }
    }

#pragma unroll
    for (int mt = 0; mt < MT; mt++) {
#pragma unroll
        for (int nt = 0; nt < NT; nt++) {
            int gc = col0 + wn + nt * 8 + t4 * 2;
            if (gc >= N) continue;
            float bias0 = bp[gc];
            float bias1 = bp[gc + 1];
#pragma unroll
            for (int h = 0; h < 2; h++) {
                int gr = row0 + wm + mt * 16 + g + h * 8;
                if (gr >= M) continue;
                float v0 = acc[mt][nt][2 * h + 0] + bias0;
                float v1 = acc[mt][nt][2 * h + 1] + bias1;
                if (act == 1) { v0 = fmaxf(v0, 0.f); v1 = fmaxf(v1, 0.f); }
                else          { v0 = tanhf(v0); v1 = tanhf(v1); }
                *reinterpret_cast<float2*>(&C[(size_t)gr * N + gc]) = make_float2(v0, v1);
            }
        }
    }
}

// ------------------------- tf32 mma.sync GEMM (small/medium layers) -------------------------
// halfOut != 0: C is a __half buffer (pitch N halfs); packed half2 stores.
template <int BN, int WM, int WN, int MINB>
__global__ __launch_bounds__(32 * (128 / WM) * (BN / WN), MINB)
void mma_gemm(const float* __restrict__ A, size_t strA,
              const float* __restrict__ W, size_t strW,
              const float* __restrict__ bias, size_t strBias, int hasBias,
              float* __restrict__ C, size_t strC,
              int M, int N, int K, int act,
              const float* __restrict__ gnoise, const int* __restrict__ gseeds,
              const int* __restrict__ Mdev, int halfOut) {
    constexpr int BM = 128, BK = 16;
    constexpr int MT = WM / 16, NT = WN / 8;
    constexpr int WARPS_M = BM / WM;
    constexpr int NTH = 32 * WARPS_M * (BN / WN);
    constexpr int AGRP = 132;
    constexpr int BGRP = 68;
    constexpr int AWORDS = (BM / 16) * (BK / 8) * AGRP;
    constexpr int BWORDS = (BK / 8) * (BN / 8) * BGRP;
    constexpr int A4 = BM * BK / 4 / NTH;
    constexpr int B4 = BK * BN / 4 / NTH;

    __shared__ uint32_t As[2][AWORDS];
    __shared__ uint32_t Bs[2][BWORDS];

    int tid = threadIdx.x, lane = tid & 31, wid = tid >> 5;
    int g = lane >> 2, t4 = lane & 3;
    int wm = (wid % WARPS_M) * WM;
    int wn = (wid / WARPS_M) * WN;

    int p = blockIdx.z;
    A += (size_t)p * strA;
    W += (size_t)p * strW;
    C += (size_t)p * strC;
    const float* bp = hasBias ? (bias + (size_t)p * strBias) : nullptr;

    int row0 = blockIdx.y * BM, col0 = blockIdx.x * BN;

    int Ml = M;
    if (Mdev) {
        Ml = *Mdev;
        if (row0 >= Ml) return;
    }

    float acc[MT][NT][4];
#pragma unroll
    for (int mt = 0; mt < MT; mt++)
#pragma unroll
        for (int nt = 0; nt < NT; nt++)
#pragma unroll
            for (int i = 0; i < 4; i++) acc[mt][nt][i] = 0.f;

    float4 va[A4], vb[B4];

    auto ldg_tile = [&](int kt) {
#pragma unroll
        for (int i = 0; i < A4; i++) {
            int idx = tid + i * NTH;
            int r = idx >> 2;
            int c4 = (idx & 3) * 4;
            int gr = row0 + r;
            va[i] = (gr < Ml) ? *reinterpret_cast<const float4*>(&A[(size_t)gr * K + kt + c4])
                              : make_float4(0.f, 0.f, 0.f, 0.f);
        }
#pragma unroll
        for (int i = 0; i < B4; i++) {
            int idx = tid + i * NTH;
            int r = idx / (BN / 4);
            int c4 = (idx % (BN / 4)) * 4;
            int gc = col0 + c4;
            vb[i] = (gc < N) ? *reinterpret_cast<const float4*>(&W[(size_t)(kt + r) * N + gc])
                             : make_float4(0.f, 0.f, 0.f, 0.f);
        }
    };
    auto sts_tile = [&](int buf) {
#pragma unroll
        for (int i = 0; i < A4; i++) {
            int idx = tid + i * NTH;
            int r = idx >> 2;
            int c4 = (idx & 3) * 4;
            int grp = ((r >> 4) * (BK / 8) + (c4 >> 3)) * AGRP;
            int reg = ((r >> 3) & 1) + (((c4 >> 2) & 1) << 1);
            int gg = r & 7;
            float f[4] = {va[i].x, va[i].y, va[i].z, va[i].w};
#pragma unroll
            for (int j = 0; j < 4; j++)
                As[buf][grp + (gg * 4 + j) * 4 + reg] = f2tf(f[j]);
        }
#pragma unroll
        for (int i = 0; i < B4; i++) {
            int idx = tid + i * NTH;
            int k = idx / (BN / 4);
            int c4 = (idx % (BN / 4)) * 4;
            int grp = ((k >> 3) * (BN / 8) + (c4 >> 3)) * BGRP;
            int reg = (k >> 2) & 1;
            int tt = k & 3;
            float f[4] = {vb[i].x, vb[i].y, vb[i].z, vb[i].w};
#pragma unroll
            for (int j = 0; j < 4; j++)
                Bs[buf][grp + (((c4 & 7) + j) * 4 + tt) * 2 + reg] = f2tf(f[j]);
        }
    };

    int ntiles = K / BK;
    ldg_tile(0);
    sts_tile(0);
    __syncthreads();
    int cur = 0;

    for (int kt = 0; kt < ntiles; kt++) {
        if (kt + 1 < ntiles) ldg_tile((kt + 1) * BK);
#pragma unroll
        for (int ksb = 0; ksb < BK / 8; ksb++) {
            uint4 af[MT];
            uint2 bf[NT];
#pragma unroll
            for (int mt = 0; mt < MT; mt++)
                af[mt] = *reinterpret_cast<const uint4*>(
                    &As[cur][(((wm >> 4) + mt) * (BK / 8) + ksb) * AGRP + lane * 4]);
#pragma unroll
            for (int nt = 0; nt < NT; nt++)
                bf[nt] = *reinterpret_cast<const uint2*>(
                    &Bs[cur][(ksb * (BN / 8) + (wn >> 3) + nt) * BGRP + lane * 2]);
#pragma unroll
            for (int mt = 0; mt < MT; mt++)
#pragma unroll
                for (int nt = 0; nt < NT; nt++)
                    mma_tf32(acc[mt][nt], reinterpret_cast<const uint32_t*>(&af[mt]),
                             reinterpret_cast<const uint32_t*>(&bf[nt]));
        }
        if (kt + 1 < ntiles) {
            sts_tile(cur ^ 1);
            __syncthreads();
            cur ^= 1;
        }
    }

#pragma unroll
    for (int mt = 0; mt < MT; mt++) {
#pragma unroll
        for (int nt = 0; nt < NT; nt++) {
            int gc = col0 + wn + nt * 8 + t4 * 2;
            if (gc >= N) continue;
            float bias0 = bp ? bp[gc] : 0.f;
            float bias1 = bp ? bp[gc + 1] : 0.f;
#pragma unroll
            for (int h = 0; h < 2; h++) {
                int gr = row0 + wm + mt * 16 + g + h * 8;
                if (gr >= Ml) continue;
                float v0 = acc[mt][nt][2 * h + 0] + bias0;
                float v1 = acc[mt][nt][2 * h + 1] + bias1;
                if (act == 1)      { v0 = fmaxf(v0, 0.f); v1 = fmaxf(v1, 0.f); }
                else if (act == 2) { v0 = (v0 > 0.f) ? v0 : 0.01f * v0;
                                     v1 = (v1 > 0.f) ? v1 : 0.01f * v1; }
                else if (act == 3) { v0 = tanhf(v0); v1 = tanhf(v1); }
                if (gnoise) {
                    const float* np = &gnoise[(size_t)gseeds[gr] * 64 + gc];
                    v0 += np[0];
                    v1 += np[1];
                }
                if (halfOut)
                    reinterpret_cast<uint32_t*>(C)[(size_t)gr * (N >> 1) + (gc >> 1)] =
                        packh2(v0, v1);
                else
                    *reinterpret_cast<float2*>(&C[(size_t)gr * N + gc]) = make_float2(v0, v1);
            }
        }
    }
}

// ------------------------- launcher -------------------------
extern "C" void kernel_launch(void* const* d_in, const int* in_sizes, int n_in,
                              void* d_out, int out_size) {
    (void)in_sizes; (void)n_in; (void)out_size;
    const float* x     = (const float*)d_in[0];
    const int*   edges = (const int*)d_in[1];
    const int*   seeds = (const int*)d_in[2];
    const float* noise = (const float*)d_in[3];
    const float* V1    = (const float*)d_in[4];
    const float* C1    = (const float*)d_in[5];
    const float* V2    = (const float*)d_in[6];
    const float* C2    = (const float*)d_in[7];
    const float* W_lin = (const float*)d_in[8];
    const float* b_lin = (const float*)d_in[9];
    const float* Wd1   = (const float*)d_in[10];
    const float* bd1   = (const float*)d_in[11];
    const float* Wd2   = (const float*)d_in[12];
    const float* bd2   = (const float*)d_in[13];
    const float* Wd3   = (const float*)d_in[14];
    const float* bd3   = (const float*)d_in[15];
    const float* Wf1   = (const float*)d_in[16];
    const float* bf1   = (const float*)d_in[17];
    const float* Wf2   = (const float*)d_in[18];
    const float* bf2   = (const float*)d_in[19];
    const float* Wf3   = (const float*)d_in[20];
    const float* bf3   = (const float*)d_in[21];
    float* out = (float*)d_out;

    void *pDeg, *pIs, *pNeed, *pCnt, *pBcat, *pH1, *pSA, *pH2, *pHs, *pD1, *pD2, *pF1, *pF2;
    cudaGetSymbolAddress(&pDeg, g_deg);
    cudaGetSymbolAddress(&pIs, g_isseed);
    cudaGetSymbolAddress(&pNeed, g_need);
    cudaGetSymbolAddress(&pCnt, g_cnt);
    cudaGetSymbolAddress(&pBcat, g_Bcat);
    cudaGetSymbolAddress(&pH1, g_h1h);
    cudaGetSymbolAddress(&pSA, g_sA);
    cudaGetSymbolAddress(&pH2, g_h2);
    cudaGetSymbolAddress(&pHs, g_hs);
    cudaGetSymbolAddress(&pD1, g_D1);
    cudaGetSymbolAddress(&pD2, g_D2);
    cudaGetSymbolAddress(&pF1, g_F1);
    cudaGetSymbolAddress(&pF2, g_F2);
    float* dBcat = (float*)pBcat;
    float* dH1   = (float*)pH1;      // __half storage; halfOut path
    float* dSA   = (float*)pSA;
    float* dH2   = (float*)pH2;
    float* dHs   = (float*)pHs;
    float* dD1   = (float*)pD1;
    float* dD2   = (float*)pD2;
    float* dF1   = (float*)pF1;
    float* dF2   = (float*)pF2;
    const int* dNcnt = ((const int*)pCnt) + 4;

    // one auxiliary stream + events for capture fork/join (created once; identical every call)
    static cudaStream_t s1 = nullptr;
    static cudaEvent_t evA, evAj, evB, evBj, evC, evCj;
    if (!s1) {
        cudaStreamCreateWithFlags(&s1, cudaStreamNonBlocking);
        cudaEventCreateWithFlags(&evA,  cudaEventDisableTiming);
        cudaEventCreateWithFlags(&evAj, cudaEventDisableTiming);
        cudaEventCreateWithFlags(&evB,  cudaEventDisableTiming);
        cudaEventCreateWithFlags(&evBj, cudaEventDisableTiming);
        cudaEventCreateWithFlags(&evC,  cudaEventDisableTiming);
        cudaEventCreateWithFlags(&evCj, cudaEventDisableTiming);
    }

    cudaMemsetAsync(pDeg, 0, sizeof(float) * RR * NN);
    cudaMemsetAsync(pIs, 0, NN);
    cudaMemsetAsync(pNeed, 0, NN);
    cudaMemsetAsync(pCnt, 0, sizeof(int) * 8);

    const int scatterBlocks = ((RR * EE / 4) * 8 + 255) / 256;

    // ---- fork A: x2h + degree counting on aux stream (independent of seedflag) ----
    cudaEventRecord(evA, 0);
    cudaStreamWaitEvent(s1, evA, 0);
    k_x2h<<<(NN * 8 + 255) / 256, 256, 0, s1>>>(x);
    k_deg<<<(RR * EE + 255) / 256, 256, 0, s1>>>(edges);
    cudaEventRecord(evAj, s1);

    k_seedflag<<<(SS + 255) / 256, 256>>>(seeds);
    k_edgepass<<<(RR * EE + 255) / 256, 256>>>(edges);
    k_nodecount<<<(NN + 255) / 256, 256>>>();
    k_zeroA<<<1024, 256>>>();
    cudaStreamWaitEvent(0, evAj, 0);           // g_xh + g_deg ready
    k_scatterA<<<scatterBlocks, 256>>>(edges);
    k_combine1<<<512, 256>>>(C1);

    // ---- fork B: zeroAseed overlapping gemm1 (both depend on combine1; disjoint buffers) ----
    cudaEventRecord(evB, 0);
    cudaStreamWaitEvent(s1, evB, 0);
    k_zeroAseed<<<(SS * RR * 8 + 255) / 256, 256, 0, s1>>>(seeds);
    cudaEventRecord(evBj, s1);

    mma_gemm<64, 32, 32, 1><<<dim3(1, (NN + 127) / 128, 1), 256>>>(
        dBcat, 0, V1, 0, nullptr, 0, 0, dH1, 0, NN, 64, 128, 1, nullptr, nullptr, dNcnt, 1);

    cudaStreamWaitEvent(0, evBj, 0);           // Ah seed rows zeroed
    k_scatterList<<<1024, 256>>>();
    k_combine2<<<(SS * 8 + 255) / 256, 256>>>(C2, seeds);
    mma_gemm<64, 32, 32, 1><<<dim3(1, SS / 128, 1), 256>>>(
        dSA, 0, V2, 0, nullptr, 0, 0, dH2, 0, SS, 64, 128, 1, nullptr, nullptr, nullptr, 0);

    // ---- linear + leaky + noise at seeds (noise fused into epilogue) ----
    mma_gemm<64, 32, 32, 1><<<dim3(1, SS / 128, 1), 256>>>(
        dH2, 0, W_lin, 0, b_lin, 0, 1, dHs, 0, SS, 64, 64, 2, noise, seeds, nullptr, 0);

    // ---- fork C: entire d branch on aux stream, overlapping the f branch ----
    cudaEventRecord(evC, 0);
    cudaStreamWaitEvent(s1, evC, 0);
    mma_gemm<128, 64, 32, 1><<<dim3(2, SS / 128, PP), 256, 0, s1>>>(
        dHs, 0, Wd1, (size_t)64 * 256, bd1, 256, 1, dD1, (size_t)SS * 256, SS, 256, 64, 2,
        nullptr, nullptr, nullptr, 0);
    mma_gemm<64, 32, 32, 1><<<dim3(1, SS / 128, PP), 256, 0, s1>>>(
        dD1, (size_t)SS * 256, Wd2, (size_t)256 * 32, bd2, 32, 1, dD2, (size_t)SS * 32,
        SS, 32, 256, 2, nullptr, nullptr, nullptr, 0);
    k_d3<<<(PP * SS + 255) / 256, 256, 0, s1>>>(Wd3, bd3, out);
    cudaEventRecord(evCj, s1);

    // ---- f branch on main stream ----
    mma_gemm<128, 64, 32, 1><<<dim3(2, SS / 128, PP), 256>>>(
        dHs, 0, Wf1, (size_t)64 * 256, bf1, 256, 1, dF1, (size_t)SS * 256, SS, 256, 64, 1,
        nullptr, nullptr, nullptr, 0);
    hmma_gemm<128, 64, 64, 2><<<dim3(16, SS / 128, PP), 128>>>(
        dF1, (size_t)SS * 256, Wf2, (size_t)256 * 2048, bf2, 2048,
        dF2, (size_t)SS * 2048, SS, 2048, 256, 1);
    hmma_gemm<128, 64, 64, 2><<<dim3(3, SS / 128, PP), 128>>>(
        dF2, (size_t)SS * 2048, Wf3, (size_t)2048 * 320, bf3, 320,
        out + PP * SS, (size_t)SS * 320, SS, 320, 2048, 3);

    // join d branch before returning (graph must have no dangling fork)
    cudaStreamWaitEvent(0, evCj, 0);
}